// round 6
// baseline (speedup 1.0000x reference)
#include <cuda_runtime.h>
#include <mma.h>
#include <cstdint>

using namespace nvcuda;

// Problem constants
#define Bn    512
#define Hh    50
#define Tt    1024
#define STATE 13
#define CTRL  4
#define LAT   128
#define HID   256
#define Dd    8            // decimation factor
#define Jn    (Tt / Dd)    // 128 sequential steps / j-tiles per batch

// ---------------- scratch (no allocations allowed) ----------------
__device__ float g_h[Bn * HID];                        // 0.5 MB
__device__ float g_E[(size_t)Bn * LAT * LAT];          // 32 MB   delta (A = I + delta)
__device__ float g_E2[(size_t)Bn * LAT * LAT];         // 32 MB   E2 = (I+E)^2 - I
__device__ float g_E4[(size_t)Bn * LAT * LAT];         // 32 MB
__device__ float g_A8[(size_t)Bn * LAT * LAT];         // 32 MB   A^8 (identity included)
__device__ float g_P[(size_t)Bn * Jn * LAT];           // 33.5 MB Horner state -> d_j
__device__ float g_Bm[Bn * LAT * CTRL];                // 1 MB
__device__ float g_z[(size_t)Bn * (Tt + 1) * LAT];     // 268.8 MB z trajectory

// ---------------- f32x2 packed FMA helpers ----------------
__device__ __forceinline__ unsigned long long pack2(float x, float y) {
    unsigned long long r;
    asm("mov.b64 %0, {%1, %2};" : "=l"(r) : "f"(x), "f"(y));
    return r;
}
__device__ __forceinline__ void unpack2(unsigned long long v, float& x, float& y) {
    asm("mov.b64 {%0, %1}, %2;" : "=f"(x), "=f"(y) : "l"(v));
}
__device__ __forceinline__ void ffma2(unsigned long long& d, unsigned long long a,
                                      unsigned long long b) {
    asm("fma.rn.f32x2 %0, %1, %2, %3;" : "=l"(d) : "l"(a), "l"(b), "l"(d));
}
__device__ __forceinline__ float dot4(float4 a, float4 b) {
    return a.x * b.x + a.y * b.y + a.z * b.z + a.w * b.w;
}

// ---------------- kernel 1: context mean + tanh MLP ----------------
__global__ void k_ctxt(const float* __restrict__ xh, const float* __restrict__ uh,
                       const float* __restrict__ Wc, const float* __restrict__ bc) {
    int b = blockIdx.x;
    int tid = threadIdx.x;
    __shared__ float m[STATE + CTRL];

    if (tid < STATE + CTRL) {
        float s = 0.f;
        if (tid < STATE) {
            const float* p = xh + (size_t)b * Hh * STATE + tid;
            for (int r = 0; r < Hh; r++) s += p[r * STATE];
        } else {
            const float* p = uh + (size_t)b * Hh * CTRL + (tid - STATE);
            for (int r = 0; r < Hh; r++) s += p[r * CTRL];
        }
        m[tid] = s * (1.0f / (float)Hh);
    }
    __syncthreads();

    float acc = bc[tid];
#pragma unroll
    for (int c = 0; c < STATE + CTRL; c++) acc += m[c] * Wc[c * HID + tid];
    g_h[b * HID + tid] = tanhf(acc);
}

// ---------------- kernel 2: E = h @ W_A + b_A  (FFMA2 tiled GEMM, NO identity) ----
#define BM 32
#define BN 256
#define BK 16
__global__ void __launch_bounds__(256)
k_gemmE(const float* __restrict__ WA, const float* __restrict__ bA) {
    __shared__ float hs[BK][BM + 4];
    __shared__ float Ws[BK][BN];
    int tid = threadIdx.x;
    int c0 = blockIdx.x * BN;
    int b0 = blockIdx.y * BM;
    int ry = tid >> 5;
    int cx = tid & 31;

    unsigned long long acc[4][4];
#pragma unroll
    for (int i = 0; i < 4; i++)
#pragma unroll
        for (int j = 0; j < 4; j++) acc[i][j] = 0ULL;

    for (int k0 = 0; k0 < HID; k0 += BK) {
        for (int idx = tid; idx < BM * BK; idx += 256) {
            int bb = idx >> 4, kk = idx & 15;
            hs[kk][bb] = g_h[(b0 + bb) * HID + k0 + kk];
        }
        for (int idx = tid; idx < (BK * BN) / 4; idx += 256) {
            int kk = idx >> 6, cc4 = idx & 63;
            *(float4*)&Ws[kk][cc4 * 4] =
                *(const float4*)&WA[(size_t)(k0 + kk) * (LAT * LAT) + c0 + cc4 * 4];
        }
        __syncthreads();
#pragma unroll
        for (int kk = 0; kk < BK; kk++) {
            unsigned long long aa[4];
#pragma unroll
            for (int i = 0; i < 4; i++) {
                float av = hs[kk][ry * 4 + i];
                aa[i] = pack2(av, av);
            }
            ulonglong2 w01 = *(const ulonglong2*)&Ws[kk][cx * 8];
            ulonglong2 w23 = *(const ulonglong2*)&Ws[kk][cx * 8 + 4];
#pragma unroll
            for (int i = 0; i < 4; i++) {
                ffma2(acc[i][0], aa[i], w01.x);
                ffma2(acc[i][1], aa[i], w01.y);
                ffma2(acc[i][2], aa[i], w23.x);
                ffma2(acc[i][3], aa[i], w23.y);
            }
        }
        __syncthreads();
    }
#pragma unroll
    for (int i = 0; i < 4; i++) {
        int b = b0 + ry * 4 + i;
        float v[8];
#pragma unroll
        for (int j = 0; j < 4; j++) unpack2(acc[i][j], v[j * 2], v[j * 2 + 1]);
#pragma unroll
        for (int j = 0; j < 8; j++) v[j] += bA[c0 + cx * 8 + j];
        float* dst = g_E + (size_t)b * (LAT * LAT) + c0 + cx * 8;
        *(float4*)dst = make_float4(v[0], v[1], v[2], v[3]);
        *(float4*)(dst + 4) = make_float4(v[4], v[5], v[6], v[7]);
    }
}

// ---------------- kernel 3: B_mat = h @ W_B + b_B ----------------
__global__ void k_gemmB(const float* __restrict__ WB, const float* __restrict__ bB) {
    int b = blockIdx.x;
    int tid = threadIdx.x;
    __shared__ float hs[HID];
    hs[tid] = g_h[b * HID + tid];
    __syncthreads();
    for (int c = tid; c < LAT * CTRL; c += 256) {
        float acc = bB[c];
#pragma unroll 8
        for (int k = 0; k < HID; k++) acc += hs[k] * WB[k * (LAT * CTRL) + c];
        g_Bm[b * (LAT * CTRL) + c] = acc;
    }
}

// ---------------- kernel: P_0[b][j][i] = c_{8j}[i] = Bm[b] @ u[b][8j] -------------
__global__ void k_cinit(const float* __restrict__ u) {
    int b = blockIdx.x;
    int tid = threadIdx.x;
    const float4* bm = (const float4*)g_Bm + b * LAT;
    for (int idx = tid; idx < Jn * LAT; idx += 256) {
        int j = idx >> 7, i = idx & 127;
        float4 u4 = *(const float4*)&u[((size_t)b * Tt + Dd * j) * CTRL];
        g_P[((size_t)b * Jn + j) * LAT + i] = dot4(bm[i], u4);
    }
}

// =====================================================================
// wmma tf32 helpers: each CTA computes one [128,128,128] batch GEMM.
// Warp layout: 8 warps = (wm 0..3: 32 rows) x (wn 0..1: 64 cols).
// Per warp: C frags fc[2 m-tiles][4 n-tiles] of m16n16k8 f32.
// =====================================================================
#define LDT 40   // smem tile leading dim (floats)

typedef wmma::fragment<wmma::matrix_a, 16, 16, 8, wmma::precision::tf32, wmma::row_major> FragA;
typedef wmma::fragment<wmma::matrix_b, 16, 16, 8, wmma::precision::tf32, wmma::col_major> FragBc;
typedef wmma::fragment<wmma::matrix_b, 16, 16, 8, wmma::precision::tf32, wmma::row_major> FragBr;
typedef wmma::fragment<wmma::accumulator, 16, 16, 8, float> FragC;

__device__ __forceinline__ void cvt_tf32_a(FragA& f) {
#pragma unroll
    for (int e = 0; e < f.num_elements; e++) f.x[e] = wmma::__float_to_tf32(f.x[e]);
}
template <typename FB>
__device__ __forceinline__ void cvt_tf32_b(FB& f) {
#pragma unroll
    for (int e = 0; e < f.num_elements; e++) f.x[e] = wmma::__float_to_tf32(f.x[e]);
}

// ---------------- squaring: out = in@in + 2*in (+I on last) ----------------
__global__ void __launch_bounds__(256, 2)
k_sq(const float* __restrict__ in, float* __restrict__ out, int addI) {
    __shared__ float sA[128 * LDT];        // A rows (also epilogue scratch)
    __shared__ float sB[32 * 136];         // B row-major chunk
    int b = blockIdx.x, tid = threadIdx.x, w = tid >> 5, lane = tid & 31;
    int wm = w & 3, wn = w >> 2;
    const float* Inb = in + (size_t)b * LAT * LAT;
    float* Outb = out + (size_t)b * LAT * LAT;

    FragC fc[2][4];
#pragma unroll
    for (int mt = 0; mt < 2; mt++)
#pragma unroll
        for (int nt = 0; nt < 4; nt++) wmma::fill_fragment(fc[mt][nt], 0.f);

    for (int k0 = 0; k0 < 128; k0 += 32) {
        for (int t = tid; t < 1024; t += 256) {
            int row = t >> 3, c4 = (t & 7) * 4;
            *(float4*)&sA[row * LDT + c4] = *(const float4*)&Inb[row * 128 + k0 + c4];
        }
        for (int t = tid; t < 1024; t += 256) {
            int kk = t >> 5, c4 = (t & 31) * 4;
            *(float4*)&sB[kk * 136 + c4] = *(const float4*)&Inb[(k0 + kk) * 128 + c4];
        }
        __syncthreads();
#pragma unroll
        for (int kk = 0; kk < 4; kk++) {
            FragA fa[2];
#pragma unroll
            for (int mt = 0; mt < 2; mt++) {
                wmma::load_matrix_sync(fa[mt], &sA[(wm * 32 + mt * 16) * LDT + kk * 8], LDT);
                cvt_tf32_a(fa[mt]);
            }
#pragma unroll
            for (int nt = 0; nt < 4; nt++) {
                FragBr fb;
                wmma::load_matrix_sync(fb, &sB[(kk * 8) * 136 + wn * 64 + nt * 16], 136);
                cvt_tf32_b(fb);
                wmma::mma_sync(fc[0][nt], fa[0], fb, fc[0][nt]);
                wmma::mma_sync(fc[1][nt], fa[1], fb, fc[1][nt]);
            }
        }
        __syncthreads();
    }
    // epilogue
    float* strip = sA + w * 640;
#pragma unroll
    for (int ph = 0; ph < 4; ph++) {
        int mt = ph >> 1, np = ph & 1;
        wmma::store_matrix_sync(strip, fc[mt][np * 2], LDT, wmma::mem_row_major);
        wmma::store_matrix_sync(strip + 16, fc[mt][np * 2 + 1], LDT, wmma::mem_row_major);
        __syncwarp();
#pragma unroll
        for (int rep = 0; rep < 4; rep++) {
            int rl = (lane >> 3) + rep * 4;
            int cl = (lane & 7) * 4;
            float4 acc4 = *(float4*)&strip[rl * LDT + cl];
            int grow = wm * 32 + mt * 16 + rl;
            int gcol = wn * 64 + np * 32 + cl;
            float4 iv = *(const float4*)&Inb[grow * 128 + gcol];
            float4 res;
            res.x = acc4.x + 2.f * iv.x + ((addI && grow == gcol + 0) ? 1.f : 0.f);
            res.y = acc4.y + 2.f * iv.y + ((addI && grow == gcol + 1) ? 1.f : 0.f);
            res.z = acc4.z + 2.f * iv.z + ((addI && grow == gcol + 2) ? 1.f : 0.f);
            res.w = acc4.w + 2.f * iv.w + ((addI && grow == gcol + 3) ? 1.f : 0.f);
            *(float4*)&Outb[grow * 128 + gcol] = res;
        }
        __syncwarp();
    }
}

// ---------------- Horner round: P <- P + P@E^T + c_{8j+r}  (in-place) ----------
__global__ void __launch_bounds__(256, 2)
k_hor(const float* __restrict__ u, int r) {
    __shared__ float sA[128 * LDT];
    __shared__ float sB[128 * LDT];
    int b = blockIdx.x, tid = threadIdx.x, w = tid >> 5, lane = tid & 31;
    int wm = w & 3, wn = w >> 2;
    float* Pb = g_P + (size_t)b * Jn * LAT;
    const float* Eb = g_E + (size_t)b * LAT * LAT;
    const float4* bm = (const float4*)g_Bm + b * LAT;

    FragC fc[2][4];
#pragma unroll
    for (int mt = 0; mt < 2; mt++)
#pragma unroll
        for (int nt = 0; nt < 4; nt++) wmma::fill_fragment(fc[mt][nt], 0.f);

    for (int k0 = 0; k0 < 128; k0 += 32) {
        for (int t = tid; t < 1024; t += 256) {
            int row = t >> 3, c4 = (t & 7) * 4;
            *(float4*)&sA[row * LDT + c4] = *(const float4*)&Pb[row * 128 + k0 + c4];
            *(float4*)&sB[row * LDT + c4] = *(const float4*)&Eb[row * 128 + k0 + c4];
        }
        __syncthreads();
#pragma unroll
        for (int kk = 0; kk < 4; kk++) {
            FragA fa[2];
#pragma unroll
            for (int mt = 0; mt < 2; mt++) {
                wmma::load_matrix_sync(fa[mt], &sA[(wm * 32 + mt * 16) * LDT + kk * 8], LDT);
                cvt_tf32_a(fa[mt]);
            }
#pragma unroll
            for (int nt = 0; nt < 4; nt++) {
                FragBc fb;   // col-major view of E => B = E^T
                wmma::load_matrix_sync(fb, &sB[(wn * 64 + nt * 16) * LDT + kk * 8], LDT);
                cvt_tf32_b(fb);
                wmma::mma_sync(fc[0][nt], fa[0], fb, fc[0][nt]);
                wmma::mma_sync(fc[1][nt], fa[1], fb, fc[1][nt]);
            }
        }
        __syncthreads();
    }
    float* strip = sA + w * 640;
#pragma unroll
    for (int ph = 0; ph < 4; ph++) {
        int mt = ph >> 1, np = ph & 1;
        wmma::store_matrix_sync(strip, fc[mt][np * 2], LDT, wmma::mem_row_major);
        wmma::store_matrix_sync(strip + 16, fc[mt][np * 2 + 1], LDT, wmma::mem_row_major);
        __syncwarp();
#pragma unroll
        for (int rep = 0; rep < 4; rep++) {
            int rl = (lane >> 3) + rep * 4;
            int cl = (lane & 7) * 4;
            float4 acc4 = *(float4*)&strip[rl * LDT + cl];
            int grow = wm * 32 + mt * 16 + rl;   // j
            int gcol = wn * 64 + np * 32 + cl;   // i
            int t = Dd * grow + r;
            float4 u4 = *(const float4*)&u[((size_t)b * Tt + t) * CTRL];
            float* outp = &Pb[grow * 128 + gcol];
            float4 pv = *(float4*)outp;
            float4 res;
            res.x = acc4.x + pv.x + dot4(bm[gcol + 0], u4);
            res.y = acc4.y + pv.y + dot4(bm[gcol + 1], u4);
            res.z = acc4.z + pv.z + dot4(bm[gcol + 2], u4);
            res.w = acc4.w + pv.w + dot4(bm[gcol + 3], u4);
            *(float4*)outp = res;
        }
        __syncwarp();
    }
}

// ---------------- recovery round: z_{8j+r} = z_{8j+r-1} + z_prev@E^T + c_{8j+r-1} --
__global__ void __launch_bounds__(256, 2)
k_rec(const float* __restrict__ u, int r) {
    __shared__ float sA[128 * LDT];
    __shared__ float sB[128 * LDT];
    int b = blockIdx.x, tid = threadIdx.x, w = tid >> 5, lane = tid & 31;
    int wm = w & 3, wn = w >> 2;
    const float* Eb = g_E + (size_t)b * LAT * LAT;
    const float4* bm = (const float4*)g_Bm + b * LAT;
    float* Zb = g_z + (size_t)b * (Tt + 1) * LAT;

    FragC fc[2][4];
#pragma unroll
    for (int mt = 0; mt < 2; mt++)
#pragma unroll
        for (int nt = 0; nt < 4; nt++) wmma::fill_fragment(fc[mt][nt], 0.f);

    for (int k0 = 0; k0 < 128; k0 += 32) {
        for (int t = tid; t < 1024; t += 256) {
            int row = t >> 3, c4 = (t & 7) * 4;
            *(float4*)&sA[row * LDT + c4] =
                *(const float4*)&Zb[((size_t)(Dd * row + r - 1)) * LAT + k0 + c4];
            *(float4*)&sB[row * LDT + c4] = *(const float4*)&Eb[row * 128 + k0 + c4];
        }
        __syncthreads();
#pragma unroll
        for (int kk = 0; kk < 4; kk++) {
            FragA fa[2];
#pragma unroll
            for (int mt = 0; mt < 2; mt++) {
                wmma::load_matrix_sync(fa[mt], &sA[(wm * 32 + mt * 16) * LDT + kk * 8], LDT);
                cvt_tf32_a(fa[mt]);
            }
#pragma unroll
            for (int nt = 0; nt < 4; nt++) {
                FragBc fb;
                wmma::load_matrix_sync(fb, &sB[(wn * 64 + nt * 16) * LDT + kk * 8], LDT);
                cvt_tf32_b(fb);
                wmma::mma_sync(fc[0][nt], fa[0], fb, fc[0][nt]);
                wmma::mma_sync(fc[1][nt], fa[1], fb, fc[1][nt]);
            }
        }
        __syncthreads();
    }
    float* strip = sA + w * 640;
#pragma unroll
    for (int ph = 0; ph < 4; ph++) {
        int mt = ph >> 1, np = ph & 1;
        wmma::store_matrix_sync(strip, fc[mt][np * 2], LDT, wmma::mem_row_major);
        wmma::store_matrix_sync(strip + 16, fc[mt][np * 2 + 1], LDT, wmma::mem_row_major);
        __syncwarp();
#pragma unroll
        for (int rep = 0; rep < 4; rep++) {
            int rl = (lane >> 3) + rep * 4;
            int cl = (lane & 7) * 4;
            float4 acc4 = *(float4*)&strip[rl * LDT + cl];
            int grow = wm * 32 + mt * 16 + rl;   // j
            int gcol = wn * 64 + np * 32 + cl;   // i
            int tsrc = Dd * grow + r - 1;
            float4 u4 = *(const float4*)&u[((size_t)b * Tt + tsrc) * CTRL];
            float4 zv = *(const float4*)&Zb[(size_t)tsrc * LAT + gcol];
            float4 res;
            res.x = acc4.x + zv.x + dot4(bm[gcol + 0], u4);
            res.y = acc4.y + zv.y + dot4(bm[gcol + 1], u4);
            res.z = acc4.z + zv.z + dot4(bm[gcol + 2], u4);
            res.w = acc4.w + zv.w + dot4(bm[gcol + 3], u4);
            *(float4*)&Zb[(size_t)(tsrc + 1) * LAT + gcol] = res;
        }
        __syncwarp();
    }
}

// ---------------- decimated sequential scan: 128 steps with A^8 ----------------
__global__ void __launch_bounds__(128, 3)
k_scan(const float* __restrict__ x_init, const float* __restrict__ Wenc,
       const float* __restrict__ benc) {
    int b = blockIdx.x;
    int i = threadIdx.x;

    __shared__ float zs[2][LAT];
    __shared__ float xi[16];

    ulonglong2 a[32];
    const ulonglong2* Ab = (const ulonglong2*)(g_A8 + (size_t)b * (LAT * LAT) + (size_t)i * LAT);
#pragma unroll
    for (int t = 0; t < 32; t++) a[t] = Ab[t];

    if (i < STATE) xi[i] = x_init[b * STATE + i];
    __syncthreads();

    float z0 = benc[i];
#pragma unroll
    for (int s = 0; s < STATE; s++) z0 += xi[s] * Wenc[s * LAT + i];
    zs[0][i] = z0;
    g_z[((size_t)b * (Tt + 1)) * LAT + i] = z0;
    __syncthreads();

    const float* dbase = g_P + (size_t)b * Jn * LAT;
    float ci = dbase[i];
    int cur = 0;

    for (int k = 0; k < Jn; k++) {
        float cnext = (k + 1 < Jn) ? dbase[(k + 1) * LAT + i] : 0.f;

        const ulonglong2* zv2 = (const ulonglong2*)zs[cur];
        unsigned long long acc0 = pack2(ci, 0.f);
        unsigned long long acc1 = 0ULL;
        unsigned long long acc2 = 0ULL;
        unsigned long long acc3 = 0ULL;
#pragma unroll
        for (int t = 0; t < 32; t += 2) {
            ulonglong2 zva = zv2[t];
            ulonglong2 zvb = zv2[t + 1];
            ffma2(acc0, a[t].x, zva.x);
            ffma2(acc1, a[t].y, zva.y);
            ffma2(acc2, a[t + 1].x, zvb.x);
            ffma2(acc3, a[t + 1].y, zvb.y);
        }
        float s0, s1, s2, s3, s4, s5, s6, s7;
        unpack2(acc0, s0, s1);
        unpack2(acc1, s2, s3);
        unpack2(acc2, s4, s5);
        unpack2(acc3, s6, s7);
        float zn = ((s0 + s2) + (s1 + s3)) + ((s4 + s6) + (s5 + s7));

        zs[cur ^ 1][i] = zn;
        g_z[((size_t)b * (Tt + 1) + Dd * (k + 1)) * LAT + i] = zn;
        ci = cnext;
        __syncthreads();
        cur ^= 1;
    }
}

// ---------------- decode + slice normalization ----------------
__global__ void k_dec(const float* __restrict__ Wdec, const float* __restrict__ bdec,
                      float* __restrict__ out) {
    __shared__ float Wt[STATE * LAT];
    __shared__ float bs[STATE];
    int tid = threadIdx.x;
    for (int idx = tid; idx < STATE * LAT; idx += 256) {
        int o = idx >> 7, c = idx & 127;
        Wt[idx] = Wdec[c * STATE + o];
    }
    if (tid < STATE) bs[tid] = bdec[tid];
    __syncthreads();

    int warp = tid >> 5, lane = tid & 31;
    size_t row = (size_t)blockIdx.x * 8 + warp;
    if (row >= (size_t)Bn * (Tt + 1)) return;

    float4 zv = ((const float4*)g_z)[row * 32 + lane];

    float s[STATE];
#pragma unroll
    for (int o = 0; o < STATE; o++) {
        float4 wv = ((const float4*)Wt)[o * 32 + lane];
        float p = zv.x * wv.x + zv.y * wv.y + zv.z * wv.z + zv.w * wv.w;
        p += __shfl_xor_sync(0xFFFFFFFFu, p, 16);
        p += __shfl_xor_sync(0xFFFFFFFFu, p, 8);
        p += __shfl_xor_sync(0xFFFFFFFFu, p, 4);
        p += __shfl_xor_sync(0xFFFFFFFFu, p, 2);
        p += __shfl_xor_sync(0xFFFFFFFFu, p, 1);
        s[o] = p + bs[o];
    }
    float nrm = sqrtf(s[3] * s[3] + s[4] * s[4] + s[5] * s[5] + s[6] * s[6]);
    float inv = 1.0f / fmaxf(nrm, 1e-12f);
#pragma unroll
    for (int o = 0; o < STATE; o++) {
        float v = s[o];
        if (o >= 3 && o < 7) v *= inv;
        if (lane == o) out[row * STATE + o] = v;
    }
}

// ---------------- launcher ----------------
extern "C" void kernel_launch(void* const* d_in, const int* in_sizes, int n_in,
                              void* d_out, int out_size) {
    const float* x_history = (const float*)d_in[0];
    const float* u_history = (const float*)d_in[1];
    const float* x_init    = (const float*)d_in[2];
    const float* u_future  = (const float*)d_in[4];
    const float* W_ctxt    = (const float*)d_in[6];
    const float* b_ctxt    = (const float*)d_in[7];
    const float* W_A       = (const float*)d_in[8];
    const float* b_A       = (const float*)d_in[9];
    const float* W_B       = (const float*)d_in[10];
    const float* b_B       = (const float*)d_in[11];
    const float* W_enc     = (const float*)d_in[12];
    const float* b_enc     = (const float*)d_in[13];
    const float* W_dec     = (const float*)d_in[14];
    const float* b_dec     = (const float*)d_in[15];
    float* out = (float*)d_out;

    float* dE;  cudaGetSymbolAddress((void**)&dE,  g_E);
    float* dE2; cudaGetSymbolAddress((void**)&dE2, g_E2);
    float* dE4; cudaGetSymbolAddress((void**)&dE4, g_E4);
    float* dA8; cudaGetSymbolAddress((void**)&dA8, g_A8);

    k_ctxt<<<Bn, 256>>>(x_history, u_history, W_ctxt, b_ctxt);
    k_gemmE<<<dim3((LAT * LAT) / BN, Bn / BM), 256>>>(W_A, b_A);
    k_gemmB<<<Bn, 256>>>(W_B, b_B);
    k_cinit<<<Bn, 256>>>(u_future);

    // A powers: E2 = (I+E)^2 - I, E4, then A8 = (I+E4)^2 (identity added)
    k_sq<<<Bn, 256>>>(dE,  dE2, 0);
    k_sq<<<Bn, 256>>>(dE2, dE4, 0);
    k_sq<<<Bn, 256>>>(dE4, dA8, 1);

    // Horner: P -> d_j over 7 rounds
    for (int r = 1; r < Dd; r++) k_hor<<<Bn, 256>>>(u_future, r);

    // sequential decimated scan (128 steps)
    k_scan<<<Bn, 128>>>(x_init, W_enc, b_enc);

    // recover intermediate states
    for (int r = 1; r < Dd; r++) k_rec<<<Bn, 256>>>(u_future, r);

    int rows = Bn * (Tt + 1);
    k_dec<<<(rows + 7) / 8, 256>>>(W_dec, b_dec, out);
}

// round 7
// speedup vs baseline: 1.4790x; 1.4790x over previous
#include <cuda_runtime.h>
#include <cstdint>

// Problem constants
#define Bn    512
#define Hh    50
#define Tt    1024
#define STATE 13
#define CTRL  4
#define LAT   128
#define HID   256
#define Dd    8            // decimation factor
#define Jn    (Tt / Dd)    // 128 sequential steps

// ---------------- scratch (no allocations allowed) ----------------
__device__ float  g_h[Bn * HID];
__device__ float  g_E [(size_t)Bn * LAT * LAT];    // delta (A = I + E)
__device__ float  g_E2[(size_t)Bn * LAT * LAT];    // (I+E)^2 - I
__device__ float  g_E4[(size_t)Bn * LAT * LAT];
__device__ float  g_A8[(size_t)Bn * LAT * LAT];    // A^8 (incl. identity)
__device__ float  g_Bm[Bn * LAT * CTRL];
__device__ float4 g_N4[Bn * Dd * LAT];             // N_k = A^k B      [b][k][i] (4 floats)
__device__ float  g_M [(size_t)Bn * Dd * LAT * STATE]; // M_r = (A^T)^r Wdec [b][r][i][o]
__device__ float  g_K [Bn * Dd * STATE * CTRL];    // K_k = Wdec^T N_k [b][k][o][c]
__device__ float  g_d [(size_t)Bn * Jn * LAT];     // d_j
__device__ float  g_z8[(size_t)Bn * (Jn + 1) * LAT];
__device__ float4 g_X4[(size_t)Bn * (Jn + 1) * 32];  // X rows 128-wide: [b][j][r*16+o]

// ---------------- f32x2 packed FMA helpers ----------------
__device__ __forceinline__ unsigned long long pack2(float x, float y) {
    unsigned long long r;
    asm("mov.b64 %0, {%1, %2};" : "=l"(r) : "f"(x), "f"(y));
    return r;
}
__device__ __forceinline__ void unpack2(unsigned long long v, float& x, float& y) {
    asm("mov.b64 {%0, %1}, %2;" : "=f"(x), "=f"(y) : "l"(v));
}
__device__ __forceinline__ void ffma2(unsigned long long& d, unsigned long long a,
                                      unsigned long long b) {
    asm("fma.rn.f32x2 %0, %1, %2, %3;" : "=l"(d) : "l"(a), "l"(b), "l"(d));
}

// ---------------- kernel 1: context mean + tanh MLP ----------------
__global__ void k_ctxt(const float* __restrict__ xh, const float* __restrict__ uh,
                       const float* __restrict__ Wc, const float* __restrict__ bc) {
    int b = blockIdx.x;
    int tid = threadIdx.x;
    __shared__ float m[STATE + CTRL];

    if (tid < STATE + CTRL) {
        float s = 0.f;
        if (tid < STATE) {
            const float* p = xh + (size_t)b * Hh * STATE + tid;
            for (int r = 0; r < Hh; r++) s += p[r * STATE];
        } else {
            const float* p = uh + (size_t)b * Hh * CTRL + (tid - STATE);
            for (int r = 0; r < Hh; r++) s += p[r * CTRL];
        }
        m[tid] = s * (1.0f / (float)Hh);
    }
    __syncthreads();

    float acc = bc[tid];
#pragma unroll
    for (int c = 0; c < STATE + CTRL; c++) acc += m[c] * Wc[c * HID + tid];
    g_h[b * HID + tid] = tanhf(acc);
}

// ---------------- kernel 2: E = h @ W_A + b_A  (FFMA2 tiled GEMM) ----------------
#define BM 32
#define BN 256
#define BK 16
__global__ void __launch_bounds__(256)
k_gemmE(const float* __restrict__ WA, const float* __restrict__ bA) {
    __align__(16) __shared__ float hs[BK][BM + 4];
    __align__(16) __shared__ float Ws[BK][BN];
    int tid = threadIdx.x;
    int c0 = blockIdx.x * BN;
    int b0 = blockIdx.y * BM;
    int ry = tid >> 5;
    int cx = tid & 31;

    unsigned long long acc[4][4];
#pragma unroll
    for (int i = 0; i < 4; i++)
#pragma unroll
        for (int j = 0; j < 4; j++) acc[i][j] = 0ULL;

    for (int k0 = 0; k0 < HID; k0 += BK) {
        for (int idx = tid; idx < BM * BK; idx += 256) {
            int bb = idx >> 4, kk = idx & 15;
            hs[kk][bb] = g_h[(b0 + bb) * HID + k0 + kk];
        }
        for (int idx = tid; idx < (BK * BN) / 4; idx += 256) {
            int kk = idx >> 6, cc4 = idx & 63;
            *(float4*)&Ws[kk][cc4 * 4] =
                *(const float4*)&WA[(size_t)(k0 + kk) * (LAT * LAT) + c0 + cc4 * 4];
        }
        __syncthreads();
#pragma unroll
        for (int kk = 0; kk < BK; kk++) {
            unsigned long long aa[4];
#pragma unroll
            for (int i = 0; i < 4; i++) {
                float av = hs[kk][ry * 4 + i];
                aa[i] = pack2(av, av);
            }
            ulonglong2 w01 = *(const ulonglong2*)&Ws[kk][cx * 8];
            ulonglong2 w23 = *(const ulonglong2*)&Ws[kk][cx * 8 + 4];
#pragma unroll
            for (int i = 0; i < 4; i++) {
                ffma2(acc[i][0], aa[i], w01.x);
                ffma2(acc[i][1], aa[i], w01.y);
                ffma2(acc[i][2], aa[i], w23.x);
                ffma2(acc[i][3], aa[i], w23.y);
            }
        }
        __syncthreads();
    }
#pragma unroll
    for (int i = 0; i < 4; i++) {
        int b = b0 + ry * 4 + i;
        float v[8];
#pragma unroll
        for (int j = 0; j < 4; j++) unpack2(acc[i][j], v[j * 2], v[j * 2 + 1]);
#pragma unroll
        for (int j = 0; j < 8; j++) v[j] += bA[c0 + cx * 8 + j];
        float* dst = g_E + (size_t)b * (LAT * LAT) + c0 + cx * 8;
        *(float4*)dst = make_float4(v[0], v[1], v[2], v[3]);
        *(float4*)(dst + 4) = make_float4(v[4], v[5], v[6], v[7]);
    }
}

// ---------------- kernel 3: B_mat = h @ W_B + b_B ----------------
__global__ void k_gemmB(const float* __restrict__ WB, const float* __restrict__ bB) {
    int b = blockIdx.x;
    int tid = threadIdx.x;
    __shared__ float hs[HID];
    hs[tid] = g_h[b * HID + tid];
    __syncthreads();
    for (int c = tid; c < LAT * CTRL; c += 256) {
        float acc = bB[c];
#pragma unroll 8
        for (int k = 0; k < HID; k++) acc += hs[k] * WB[k * (LAT * CTRL) + c];
        g_Bm[b * (LAT * CTRL) + c] = acc;
    }
}

// ---------------- scalar FFMA2 squaring: out = in@in + 2*in (+I) ----------------
#define SQP 132
__global__ void __launch_bounds__(256, 2)
k_sq(const float* __restrict__ in, float* __restrict__ out, int addI) {
    __align__(16) __shared__ float sA[16 * SQP];  // [kk][row]
    __align__(16) __shared__ float sB[16 * SQP];  // [kk][col]
    int b = blockIdx.x, tid = threadIdx.x;
    const float* Inb = in + (size_t)b * LAT * LAT;
    float* Outb = out + (size_t)b * LAT * LAT;
    int ry = tid >> 4, cx = tid & 15;   // 16x16 threads, 8x8 tile

    __align__(16) unsigned long long acc[8][4];
#pragma unroll
    for (int q = 0; q < 8; q++)
#pragma unroll
        for (int p = 0; p < 4; p++) acc[q][p] = 0ULL;

    for (int k0 = 0; k0 < 128; k0 += 16) {
        __syncthreads();
        {   // sA[kk][row] = in[row][k0+kk]
            int row = tid >> 1, kb = (tid & 1) * 8;
            float4 v0 = *(const float4*)&Inb[row * 128 + k0 + kb];
            float4 v1 = *(const float4*)&Inb[row * 128 + k0 + kb + 4];
            sA[(kb + 0) * SQP + row] = v0.x; sA[(kb + 1) * SQP + row] = v0.y;
            sA[(kb + 2) * SQP + row] = v0.z; sA[(kb + 3) * SQP + row] = v0.w;
            sA[(kb + 4) * SQP + row] = v1.x; sA[(kb + 5) * SQP + row] = v1.y;
            sA[(kb + 6) * SQP + row] = v1.z; sA[(kb + 7) * SQP + row] = v1.w;
        }
        {   // sB[kk][col] = in[k0+kk][col]
            int kk = tid >> 4, cb = (tid & 15) * 8;
            *(float4*)&sB[kk * SQP + cb]     = *(const float4*)&Inb[(k0 + kk) * 128 + cb];
            *(float4*)&sB[kk * SQP + cb + 4] = *(const float4*)&Inb[(k0 + kk) * 128 + cb + 4];
        }
        __syncthreads();
#pragma unroll
        for (int kk = 0; kk < 16; kk++) {
            float4 a0 = *(float4*)&sA[kk * SQP + ry * 8];
            float4 a1 = *(float4*)&sA[kk * SQP + ry * 8 + 4];
            ulonglong2 b0 = *(ulonglong2*)&sB[kk * SQP + cx * 8];
            ulonglong2 b1 = *(ulonglong2*)&sB[kk * SQP + cx * 8 + 4];
            unsigned long long bb[4] = {b0.x, b0.y, b1.x, b1.y};
            float av[8] = {a0.x, a0.y, a0.z, a0.w, a1.x, a1.y, a1.z, a1.w};
#pragma unroll
            for (int q = 0; q < 8; q++) {
                unsigned long long a2 = pack2(av[q], av[q]);
#pragma unroll
                for (int p = 0; p < 4; p++) ffma2(acc[q][p], a2, bb[p]);
            }
        }
    }
#pragma unroll
    for (int q = 0; q < 8; q++) {
        int row = ry * 8 + q;
        float v[8];
#pragma unroll
        for (int p = 0; p < 4; p++) unpack2(acc[q][p], v[p * 2], v[p * 2 + 1]);
        const float* ip = &Inb[row * 128 + cx * 8];
        float4 i0 = *(const float4*)ip, i1 = *(const float4*)(ip + 4);
        v[0] += 2.f * i0.x; v[1] += 2.f * i0.y; v[2] += 2.f * i0.z; v[3] += 2.f * i0.w;
        v[4] += 2.f * i1.x; v[5] += 2.f * i1.y; v[6] += 2.f * i1.z; v[7] += 2.f * i1.w;
        if (addI) {
            int c0 = cx * 8;
            if (row >= c0 && row < c0 + 8) v[row - c0] += 1.f;
        }
        float* op = &Outb[row * 128 + cx * 8];
        *(float4*)op = make_float4(v[0], v[1], v[2], v[3]);
        *(float4*)(op + 4) = make_float4(v[4], v[5], v[6], v[7]);
    }
}

// ---------------- per-batch small recurrences: M_r, N_k, K_k ----------------
// M_r = M_{r-1} + E^T M_{r-1} (E row-tiles);  N_k = N_{k-1} + E N_{k-1} (E col-tiles)
__global__ void __launch_bounds__(256)
k_mn(const float* __restrict__ Wdec) {
    __shared__ float sE[128 * 33];          // union: row-tile [32][129] / col-tile [128][33]
    __shared__ float sM[LAT * STATE];
    __shared__ float sN[LAT * CTRL];
    int b = blockIdx.x, tid = threadIdx.x;
    const float* Eb = g_E + (size_t)b * LAT * LAT;

    for (int t = tid; t < LAT * STATE; t += 256) {
        float v = Wdec[t];
        sM[t] = v;
        g_M[(size_t)(b * Dd + 0) * LAT * STATE + t] = v;
    }
    for (int t = tid; t < LAT * CTRL; t += 256) {
        float v = g_Bm[b * LAT * CTRL + t];
        sN[t] = v;
        ((float*)g_N4)[(size_t)(b * Dd + 0) * LAT * CTRL + t] = v;
    }
    __syncthreads();
    if (tid < STATE * CTRL) {   // K_0
        int o = tid >> 2, c = tid & 3;
        float acc = 0.f;
        for (int i = 0; i < LAT; i++) acc += Wdec[i * STATE + o] * sN[i * CTRL + c];
        g_K[(b * Dd + 0) * STATE * CTRL + tid] = acc;
    }

    // ---- M phase ----
    int i = tid & 127, oh = tid >> 7;
    int ob = oh ? 7 : 0, on = oh ? 6 : 7;
    for (int r = 1; r < Dd; r++) {
        float acc[7];
#pragma unroll
        for (int oo = 0; oo < 7; oo++) acc[oo] = (oo < on) ? sM[i * STATE + ob + oo] : 0.f;
        for (int l0 = 0; l0 < LAT; l0 += 32) {
            __syncthreads();
            for (int t = tid; t < 32 * 128; t += 256) {
                int l = t >> 7, i2 = t & 127;
                sE[l * 129 + i2] = Eb[(size_t)(l0 + l) * LAT + i2];
            }
            __syncthreads();
            for (int l = 0; l < 32; l++) {
                float e = sE[l * 129 + i];
#pragma unroll
                for (int oo = 0; oo < 7; oo++)
                    if (oo < on) acc[oo] += e * sM[(l0 + l) * STATE + ob + oo];
            }
        }
        __syncthreads();
        for (int oo = 0; oo < on; oo++) sM[i * STATE + ob + oo] = acc[oo];
        __syncthreads();
        for (int t = tid; t < LAT * STATE; t += 256)
            g_M[(size_t)(b * Dd + r) * LAT * STATE + t] = sM[t];
    }

    // ---- N phase ----
    for (int k = 1; k < Dd; k++) {
        float accN[4] = {0.f, 0.f, 0.f, 0.f};
        if (tid < 128)
#pragma unroll
            for (int c = 0; c < 4; c++) accN[c] = sN[tid * 4 + c];
        for (int l0 = 0; l0 < LAT; l0 += 32) {
            __syncthreads();
            for (int t = tid; t < 128 * 32; t += 256) {
                int i2 = t >> 5, l = t & 31;
                sE[i2 * 33 + l] = Eb[(size_t)i2 * LAT + l0 + l];
            }
            __syncthreads();
            if (tid < 128)
                for (int l = 0; l < 32; l++) {
                    float e = sE[tid * 33 + l];
#pragma unroll
                    for (int c = 0; c < 4; c++) accN[c] += e * sN[(l0 + l) * 4 + c];
                }
        }
        __syncthreads();
        if (tid < 128)
#pragma unroll
            for (int c = 0; c < 4; c++) sN[tid * 4 + c] = accN[c];
        __syncthreads();
        for (int t = tid; t < LAT * CTRL; t += 256)
            ((float*)g_N4)[(size_t)(b * Dd + k) * LAT * CTRL + t] = sN[t];
        if (tid < STATE * CTRL) {
            int o = tid >> 2, c = tid & 3;
            float acc = 0.f;
            for (int ii = 0; ii < LAT; ii++) acc += Wdec[ii * STATE + o] * sN[ii * CTRL + c];
            g_K[(b * Dd + k) * STATE * CTRL + tid] = acc;
        }
        __syncthreads();
    }
}

// ---------------- d_j = sum_r N_{7-r} u_{8j+r} ----------------
__global__ void k_dj(const float* __restrict__ u) {
    int j = blockIdx.x, b = blockIdx.y, i = threadIdx.x;
    __shared__ float4 su[8];
    if (i < 8) su[i] = *(const float4*)&u[((size_t)b * Tt + j * 8 + i) * CTRL];
    __syncthreads();
    float acc = 0.f;
#pragma unroll
    for (int r = 0; r < 8; r++) {
        float4 n = g_N4[(b * Dd + (7 - r)) * LAT + i];
        float4 uu = su[r];
        acc += n.x * uu.x + n.y * uu.y + n.z * uu.z + n.w * uu.w;
    }
    g_d[((size_t)b * Jn + j) * LAT + i] = acc;
}

// ---------------- decimated scan: 128 steps with A^8 ----------------
__global__ void __launch_bounds__(128, 3)
k_scan(const float* __restrict__ x_init, const float* __restrict__ Wenc,
       const float* __restrict__ benc) {
    int b = blockIdx.x;
    int i = threadIdx.x;

    __shared__ float zs[2][LAT];
    __shared__ float xi[16];

    ulonglong2 a[32];
    const ulonglong2* Ab = (const ulonglong2*)(g_A8 + (size_t)b * (LAT * LAT) + (size_t)i * LAT);
#pragma unroll
    for (int t = 0; t < 32; t++) a[t] = Ab[t];

    if (i < STATE) xi[i] = x_init[b * STATE + i];
    __syncthreads();

    float z0 = benc[i];
#pragma unroll
    for (int s = 0; s < STATE; s++) z0 += xi[s] * Wenc[s * LAT + i];
    zs[0][i] = z0;
    g_z8[(size_t)b * (Jn + 1) * LAT + i] = z0;
    __syncthreads();

    const float* db = g_d + (size_t)b * Jn * LAT;
    float ci = db[i];
    int cur = 0;

    for (int k = 0; k < Jn; k++) {
        float cnext = (k + 1 < Jn) ? db[(k + 1) * LAT + i] : 0.f;

        const ulonglong2* zv2 = (const ulonglong2*)zs[cur];
        unsigned long long acc0 = pack2(ci, 0.f);
        unsigned long long acc1 = 0ULL, acc2 = 0ULL, acc3 = 0ULL;
#pragma unroll
        for (int t = 0; t < 32; t += 2) {
            ulonglong2 zva = zv2[t];
            ulonglong2 zvb = zv2[t + 1];
            ffma2(acc0, a[t].x, zva.x);
            ffma2(acc1, a[t].y, zva.y);
            ffma2(acc2, a[t + 1].x, zvb.x);
            ffma2(acc3, a[t + 1].y, zvb.y);
        }
        float s0, s1, s2, s3, s4, s5, s6, s7;
        unpack2(acc0, s0, s1); unpack2(acc1, s2, s3);
        unpack2(acc2, s4, s5); unpack2(acc3, s6, s7);
        float zn = ((s0 + s2) + (s1 + s3)) + ((s4 + s6) + (s5 + s7));

        zs[cur ^ 1][i] = zn;
        g_z8[((size_t)b * (Jn + 1) + k + 1) * LAT + i] = zn;
        ci = cnext;
        __syncthreads();
        cur ^= 1;
    }
}

// ---------------- X GEMM: X[j][r*16+o] = z8[j] . M_r[:,o] ----------------
#define XP 132
__global__ void __launch_bounds__(256)
k_xg() {
    __align__(16) __shared__ float sZ[32 * XP];   // [kk][j], j=0..128
    __align__(16) __shared__ float sM2[32 * XP];  // [kk][r*16+o]
    int b = blockIdx.x, tid = threadIdx.x;
    int ry = tid >> 3;   // 0..31 -> rows j = ry*4..+3
    int cx = tid & 7;    // r = cx, cols cx*16..+15

    __align__(16) unsigned long long acc2[4][8];
#pragma unroll
    for (int q = 0; q < 4; q++)
#pragma unroll
        for (int p = 0; p < 8; p++) acc2[q][p] = 0ULL;
    float acc128 = 0.f;
    int r13 = 0, o13 = 0;
    if (tid < 104) { r13 = tid / 13; o13 = tid % 13; }

    for (int k0 = 0; k0 < 128; k0 += 32) {
        __syncthreads();
        for (int t = tid; t < 129 * 32; t += 256) {
            int j = t >> 5, kk = t & 31;
            sZ[kk * XP + j] = g_z8[((size_t)b * (Jn + 1) + j) * LAT + k0 + kk];
        }
        for (int t = tid; t < 32 * 128; t += 256) {
            int kk = t >> 7, col = t & 127;
            int r = col >> 4, o = col & 15;
            sM2[kk * XP + col] =
                (o < STATE) ? g_M[((size_t)(b * Dd + r) * LAT + k0 + kk) * STATE + o] : 0.f;
        }
        __syncthreads();
#pragma unroll
        for (int kk = 0; kk < 32; kk++) {
            float4 a4 = *(float4*)&sZ[kk * XP + ry * 4];
            ulonglong2 bb0 = *(ulonglong2*)&sM2[kk * XP + cx * 16];
            ulonglong2 bb1 = *(ulonglong2*)&sM2[kk * XP + cx * 16 + 4];
            ulonglong2 bb2 = *(ulonglong2*)&sM2[kk * XP + cx * 16 + 8];
            ulonglong2 bb3 = *(ulonglong2*)&sM2[kk * XP + cx * 16 + 12];
            unsigned long long bb[8] = {bb0.x, bb0.y, bb1.x, bb1.y, bb2.x, bb2.y, bb3.x, bb3.y};
            float av[4] = {a4.x, a4.y, a4.z, a4.w};
#pragma unroll
            for (int q = 0; q < 4; q++) {
                unsigned long long a2 = pack2(av[q], av[q]);
#pragma unroll
                for (int p = 0; p < 8; p++) ffma2(acc2[q][p], a2, bb[p]);
            }
        }
        if (tid < 104) {
            float accl = 0.f;
            for (int kk = 0; kk < 32; kk++)
                accl += sZ[kk * XP + 128] * sM2[kk * XP + r13 * 16 + o13];
            acc128 += accl;
        }
    }
    float* X = (float*)g_X4;
#pragma unroll
    for (int q = 0; q < 4; q++) {
        int j = ry * 4 + q;
        size_t base = ((size_t)b * (Jn + 1) + j) * 128 + cx * 16;
        *(float4*)&X[base]      = *(float4*)&acc2[q][0];
        *(float4*)&X[base + 4]  = *(float4*)&acc2[q][2];
        *(float4*)&X[base + 8]  = *(float4*)&acc2[q][4];
        *(float4*)&X[base + 12] = *(float4*)&acc2[q][6];
    }
    if (tid < 104)
        X[((size_t)b * (Jn + 1) + 128) * 128 + r13 * 16 + o13] = acc128;
}

// ---------------- final: u-corrections + bias + normalize + write out ----------------
__global__ void __launch_bounds__(256)
k_norm(const float* __restrict__ u, const float* __restrict__ bdec,
       float* __restrict__ outp) {
    int b = blockIdx.y, t0 = blockIdx.x * 256, tid = threadIdx.x;
    __shared__ float sK[Dd * STATE * CTRL];
    __shared__ float4 su[256];
    __shared__ float sb[STATE];
    __shared__ float sO[256 * STATE];

    for (int q = tid; q < Dd * STATE * CTRL; q += 256) sK[q] = g_K[b * Dd * STATE * CTRL + q];
    if (t0 + tid < Tt) su[tid] = *(const float4*)&u[((size_t)b * Tt + t0 + tid) * CTRL];
    if (tid < STATE) sb[tid] = bdec[tid];
    __syncthreads();

    int t = t0 + tid;
    if (t <= Tt) {
        int j = t >> 3, r = t & 7;
        const float* xr = (const float*)g_X4 + ((size_t)b * (Jn + 1) + j) * 128 + r * 16;
        float4 x0 = *(const float4*)&xr[0];
        float4 x1 = *(const float4*)&xr[4];
        float4 x2 = *(const float4*)&xr[8];
        float4 x3 = *(const float4*)&xr[12];
        float x[13] = {x0.x, x0.y, x0.z, x0.w, x1.x, x1.y, x1.z, x1.w,
                       x2.x, x2.y, x2.z, x2.w, x3.x};
#pragma unroll
        for (int o = 0; o < STATE; o++) x[o] += sb[o];
        for (int s = 0; s < r; s++) {
            float4 uu = su[tid - r + s];
            const float* Kp = &sK[(r - 1 - s) * STATE * CTRL];
#pragma unroll
            for (int o = 0; o < STATE; o++)
                x[o] += Kp[o * 4 + 0] * uu.x + Kp[o * 4 + 1] * uu.y +
                        Kp[o * 4 + 2] * uu.z + Kp[o * 4 + 3] * uu.w;
        }
        float nrm = sqrtf(x[3] * x[3] + x[4] * x[4] + x[5] * x[5] + x[6] * x[6]);
        float inv = 1.0f / fmaxf(nrm, 1e-12f);
        x[3] *= inv; x[4] *= inv; x[5] *= inv; x[6] *= inv;
#pragma unroll
        for (int o = 0; o < STATE; o++) sO[tid * STATE + o] = x[o];
    }
    __syncthreads();
    int nrow = Tt + 1 - t0;
    if (nrow > 256) nrow = 256;
    if (nrow < 0) nrow = 0;
    for (int q = tid; q < nrow * STATE; q += 256)
        outp[((size_t)b * (Tt + 1) + t0) * STATE + q] = sO[q];
}

// ---------------- launcher ----------------
extern "C" void kernel_launch(void* const* d_in, const int* in_sizes, int n_in,
                              void* d_out, int out_size) {
    const float* x_history = (const float*)d_in[0];
    const float* u_history = (const float*)d_in[1];
    const float* x_init    = (const float*)d_in[2];
    const float* u_future  = (const float*)d_in[4];
    const float* W_ctxt    = (const float*)d_in[6];
    const float* b_ctxt    = (const float*)d_in[7];
    const float* W_A       = (const float*)d_in[8];
    const float* b_A       = (const float*)d_in[9];
    const float* W_B       = (const float*)d_in[10];
    const float* b_B       = (const float*)d_in[11];
    const float* W_enc     = (const float*)d_in[12];
    const float* b_enc     = (const float*)d_in[13];
    const float* W_dec     = (const float*)d_in[14];
    const float* b_dec     = (const float*)d_in[15];
    float* out = (float*)d_out;

    float* dE;  cudaGetSymbolAddress((void**)&dE,  g_E);
    float* dE2; cudaGetSymbolAddress((void**)&dE2, g_E2);
    float* dE4; cudaGetSymbolAddress((void**)&dE4, g_E4);
    float* dA8; cudaGetSymbolAddress((void**)&dA8, g_A8);

    k_ctxt<<<Bn, 256>>>(x_history, u_history, W_ctxt, b_ctxt);
    k_gemmE<<<dim3((LAT * LAT) / BN, Bn / BM), 256>>>(W_A, b_A);
    k_gemmB<<<Bn, 256>>>(W_B, b_B);

    k_sq<<<Bn, 256>>>(dE,  dE2, 0);
    k_sq<<<Bn, 256>>>(dE2, dE4, 0);
    k_sq<<<Bn, 256>>>(dE4, dA8, 1);

    k_mn<<<Bn, 256>>>(W_dec);
    k_dj<<<dim3(Jn, Bn), 128>>>(u_future);

    k_scan<<<Bn, 128>>>(x_init, W_enc, b_enc);

    k_xg<<<Bn, 256>>>();
    k_norm<<<dim3(5, Bn), 256>>>(u_future, b_dec, out);
}

// round 8
// speedup vs baseline: 1.7962x; 1.2145x over previous
#include <cuda_runtime.h>
#include <mma.h>
#include <cstdint>

using namespace nvcuda;

// Problem constants
#define Bn    512
#define Hh    50
#define Tt    1024
#define STATE 13
#define CTRL  4
#define LAT   128
#define HID   256
#define Dd    8            // decimation factor
#define Jn    (Tt / Dd)    // 128 sequential steps

// ---------------- scratch (no allocations allowed) ----------------
__device__ float  g_h[Bn * HID];
__device__ float  g_E [(size_t)Bn * LAT * LAT];    // raw h@W_A product (bias NOT added)
__device__ float  g_A8[(size_t)Bn * LAT * LAT];    // A^8 (incl. identity)
__device__ float  g_Bm[Bn * LAT * CTRL];
__device__ float  g_M [(size_t)Bn * Dd * LAT * STATE]; // M_r = (A^T)^r Wdec
__device__ float  g_K [Bn * Dd * STATE * CTRL];    // K_k = Wdec^T A^k B
__device__ float  g_d [(size_t)Bn * Jn * LAT];     // d_j
__device__ float  g_z8[(size_t)Bn * (Jn + 1) * LAT];
__device__ float4 g_X4[(size_t)Bn * (Jn + 1) * 32];  // X rows 128-wide: [b][j][r*16+o]

// ---------------- f32x2 packed FMA helpers ----------------
__device__ __forceinline__ unsigned long long pack2(float x, float y) {
    unsigned long long r;
    asm("mov.b64 %0, {%1, %2};" : "=l"(r) : "f"(x), "f"(y));
    return r;
}
__device__ __forceinline__ void unpack2(unsigned long long v, float& x, float& y) {
    asm("mov.b64 {%0, %1}, %2;" : "=f"(x), "=f"(y) : "l"(v));
}
__device__ __forceinline__ void ffma2(unsigned long long& d, unsigned long long a,
                                      unsigned long long b) {
    asm("fma.rn.f32x2 %0, %1, %2, %3;" : "=l"(d) : "l"(a), "l"(b), "l"(d));
}
__device__ __forceinline__ float dot4(float4 a, float4 b) {
    return a.x * b.x + a.y * b.y + a.z * b.z + a.w * b.w;
}

// ---------------- wmma types ----------------
typedef wmma::fragment<wmma::matrix_a, 16, 16, 8, wmma::precision::tf32, wmma::row_major> FragA;
typedef wmma::fragment<wmma::matrix_b, 16, 16, 8, wmma::precision::tf32, wmma::row_major> FragBr;
typedef wmma::fragment<wmma::accumulator, 16, 16, 8, float> FragC;

__device__ __forceinline__ void cvt_tf32_a(FragA& f) {
#pragma unroll
    for (int e = 0; e < f.num_elements; e++) f.x[e] = wmma::__float_to_tf32(f.x[e]);
}
__device__ __forceinline__ void cvt_tf32_b(FragBr& f) {
#pragma unroll
    for (int e = 0; e < f.num_elements; e++) f.x[e] = wmma::__float_to_tf32(f.x[e]);
}
// split src into hi (tf32) + lo (tf32 of residual); src becomes hi
__device__ __forceinline__ void split_a(FragA& src, FragA& lo) {
#pragma unroll
    for (int e = 0; e < src.num_elements; e++) {
        float a = src.x[e];
        float hi = wmma::__float_to_tf32(a);
        src.x[e] = hi;
        lo.x[e] = wmma::__float_to_tf32(a - hi);
    }
}
__device__ __forceinline__ void split_b(FragBr& src, FragBr& lo) {
#pragma unroll
    for (int e = 0; e < src.num_elements; e++) {
        float a = src.x[e];
        float hi = wmma::__float_to_tf32(a);
        src.x[e] = hi;
        lo.x[e] = wmma::__float_to_tf32(a - hi);
    }
}

// ---------------- kernel 1: context mean + tanh MLP ----------------
__global__ void k_ctxt(const float* __restrict__ xh, const float* __restrict__ uh,
                       const float* __restrict__ Wc, const float* __restrict__ bc) {
    int b = blockIdx.x;
    int tid = threadIdx.x;
    __shared__ float m[STATE + CTRL];

    if (tid < STATE + CTRL) {
        float s = 0.f;
        if (tid < STATE) {
            const float* p = xh + (size_t)b * Hh * STATE + tid;
        for (int r = 0; r < Hh; r++) s += p[r * STATE];
        } else {
            const float* p = uh + (size_t)b * Hh * CTRL + (tid - STATE);
            for (int r = 0; r < Hh; r++) s += p[r * CTRL];
        }
        m[tid] = s * (1.0f / (float)Hh);
    }
    __syncthreads();

    float acc = bc[tid];
#pragma unroll
    for (int c = 0; c < STATE + CTRL; c++) acc += m[c] * Wc[c * HID + tid];
    g_h[b * HID + tid] = tanhf(acc);
}

// ---------------- kernel 2: E = h @ W_A (tf32 3-term split, no bias) ----------------
// grid (128 n-tiles, 4 m-tiles). C[512,16384]. Stores fragments straight to g_E.
__global__ void __launch_bounds__(256)
k_gemmE_tc(const float* __restrict__ WA) {
    __shared__ float sA[128 * 36];
    __shared__ float sB[32 * 132];
    int tid = threadIdx.x, w = tid >> 5;
    int wm = w & 3, wn = w >> 2;
    int n0g = blockIdx.x * 128;
    int m0g = blockIdx.y * 128;

    FragC fc[2][4];
#pragma unroll
    for (int mt = 0; mt < 2; mt++)
#pragma unroll
        for (int nt = 0; nt < 4; nt++) wmma::fill_fragment(fc[mt][nt], 0.f);

    for (int k0 = 0; k0 < HID; k0 += 32) {
        __syncthreads();
#pragma unroll
        for (int p = 0; p < 4; p++) {
            int idx = tid + p * 256;
            int row = idx >> 3, kq = (idx & 7) * 4;
            *(float4*)&sA[row * 36 + kq] =
                *(const float4*)&g_h[(m0g + row) * HID + k0 + kq];
        }
#pragma unroll
        for (int p = 0; p < 4; p++) {
            int idx = tid + p * 256;
            int kkb = idx >> 5, c4 = (idx & 31) * 4;
            *(float4*)&sB[kkb * 132 + c4] =
                *(const float4*)&WA[(size_t)(k0 + kkb) * (LAT * LAT) + n0g + c4];
        }
        __syncthreads();
#pragma unroll
        for (int kk8 = 0; kk8 < 4; kk8++) {
            FragA fah[2], fal[2];
#pragma unroll
            for (int mt = 0; mt < 2; mt++) {
                wmma::load_matrix_sync(fah[mt], &sA[(wm * 32 + mt * 16) * 36 + kk8 * 8], 36);
                split_a(fah[mt], fal[mt]);
            }
#pragma unroll
            for (int nt = 0; nt < 4; nt++) {
                FragBr fbh, fbl;
                wmma::load_matrix_sync(fbh, &sB[(kk8 * 8) * 132 + wn * 64 + nt * 16], 132);
                split_b(fbh, fbl);
#pragma unroll
                for (int mt = 0; mt < 2; mt++) {
                    wmma::mma_sync(fc[mt][nt], fah[mt], fbl, fc[mt][nt]);
                    wmma::mma_sync(fc[mt][nt], fal[mt], fbh, fc[mt][nt]);
                    wmma::mma_sync(fc[mt][nt], fah[mt], fbh, fc[mt][nt]);
                }
            }
        }
    }
#pragma unroll
    for (int mt = 0; mt < 2; mt++)
#pragma unroll
        for (int nt = 0; nt < 4; nt++)
            wmma::store_matrix_sync(
                &g_E[(size_t)(m0g + wm * 32 + mt * 16) * (LAT * LAT) +
                     n0g + wn * 64 + nt * 16],
                fc[mt][nt], LAT * LAT, wmma::mem_row_major);
}

// ---------------- kernel 3: B_mat = h @ W_B + b_B ----------------
__global__ void k_gemmB(const float* __restrict__ WB, const float* __restrict__ bB) {
    int b = blockIdx.x;
    int tid = threadIdx.x;
    __shared__ float hs[HID];
    hs[tid] = g_h[b * HID + tid];
    __syncthreads();
    for (int c = tid; c < LAT * CTRL; c += 256) {
        float acc = bB[c];
#pragma unroll 8
        for (int k = 0; k < HID; k++) acc += hs[k] * WB[k * (LAT * CTRL) + c];
        g_Bm[b * (LAT * CTRL) + c] = acc;
    }
}

// ---------------- fused 3 squarings in smem (tf32): A^8 ----------------
// One CTA per batch. X = E (+bias). 3 rounds of Y = X@X + 2X (+I last). 
#define PLD 132
__global__ void __launch_bounds__(256)
k_pow(const float* __restrict__ bA) {
    extern __shared__ float dsm[];
    float* sX = dsm;
    float* sY = dsm + 128 * PLD;
    int b = blockIdx.x, tid = threadIdx.x, w = tid >> 5;
    int wm = w & 3, wn = w >> 2;
    const float* Eb = g_E + (size_t)b * (LAT * LAT);

    // load E + bias
#pragma unroll
    for (int p = 0; p < 16; p++) {
        int idx = tid + p * 256;
        int row = idx >> 5, c4 = (idx & 31) * 4;
        float4 e = *(const float4*)&Eb[row * 128 + c4];
        float4 bb = *(const float4*)&bA[row * 128 + c4];
        e.x += bb.x; e.y += bb.y; e.z += bb.z; e.w += bb.w;
        *(float4*)&sX[row * PLD + c4] = e;
    }
    __syncthreads();

    float* pX = sX;
    float* pY = sY;
    for (int rnd = 0; rnd < 3; rnd++) {
        FragC fc[2][4];
#pragma unroll
        for (int mt = 0; mt < 2; mt++)
#pragma unroll
            for (int nt = 0; nt < 4; nt++) wmma::fill_fragment(fc[mt][nt], 0.f);

#pragma unroll 4
        for (int kk = 0; kk < 16; kk++) {
            FragA fa[2];
#pragma unroll
            for (int mt = 0; mt < 2; mt++) {
                wmma::load_matrix_sync(fa[mt], &pX[(wm * 32 + mt * 16) * PLD + kk * 8], PLD);
                cvt_tf32_a(fa[mt]);
            }
#pragma unroll
            for (int nt = 0; nt < 4; nt++) {
                FragBr fb;
                wmma::load_matrix_sync(fb, &pX[(kk * 8) * PLD + wn * 64 + nt * 16], PLD);
                cvt_tf32_b(fb);
                wmma::mma_sync(fc[0][nt], fa[0], fb, fc[0][nt]);
                wmma::mma_sync(fc[1][nt], fa[1], fb, fc[1][nt]);
            }
        }
#pragma unroll
        for (int mt = 0; mt < 2; mt++)
#pragma unroll
            for (int nt = 0; nt < 4; nt++)
                wmma::store_matrix_sync(&pY[(wm * 32 + mt * 16) * PLD + wn * 64 + nt * 16],
                                        fc[mt][nt], PLD, wmma::mem_row_major);
        __syncthreads();
        // elementwise: Y += 2X (+I on last round)
#pragma unroll
        for (int p = 0; p < 16; p++) {
            int idx = tid + p * 256;
            int row = idx >> 5, c4 = (idx & 31) * 4;
            float4 y = *(float4*)&pY[row * PLD + c4];
            float4 x = *(float4*)&pX[row * PLD + c4];
            y.x += 2.f * x.x; y.y += 2.f * x.y; y.z += 2.f * x.z; y.w += 2.f * x.w;
            if (rnd == 2) {
                int dq = row - c4;
                if (dq >= 0 && dq < 4) ((float*)&y)[dq] += 1.f;
            }
            *(float4*)&pY[row * PLD + c4] = y;
        }
        __syncthreads();
        float* t = pX; pX = pY; pY = t;
    }

    float* A8b = g_A8 + (size_t)b * (LAT * LAT);
#pragma unroll
    for (int p = 0; p < 16; p++) {
        int idx = tid + p * 256;
        int row = idx >> 5, c4 = (idx & 31) * 4;
        *(float4*)&A8b[row * 128 + c4] = *(float4*)&pX[row * PLD + c4];
    }
}

// ---------------- fused M/N/K/d with E smem-resident ----------------
__global__ void __launch_bounds__(256)
k_mnd(const float* __restrict__ bA, const float* __restrict__ Wdec,
      const float* __restrict__ u) {
    extern __shared__ float dsm[];
    float* sE    = dsm;                    // 128*132
    float* sM    = sE + 128 * PLD;         // 128*13
    float* sNall = sM + 128 * STATE;       // 8*128*4
    float* su    = sNall + 8 * 128 * 4;    // 1024*4
    int b = blockIdx.x, tid = threadIdx.x;
    const float* Eb = g_E + (size_t)b * (LAT * LAT);

    // load E + bias
#pragma unroll
    for (int p = 0; p < 16; p++) {
        int idx = tid + p * 256;
        int row = idx >> 5, c4 = (idx & 31) * 4;
        float4 e = *(const float4*)&Eb[row * 128 + c4];
        float4 bb = *(const float4*)&bA[row * 128 + c4];
        e.x += bb.x; e.y += bb.y; e.z += bb.z; e.w += bb.w;
        *(float4*)&sE[row * PLD + c4] = e;
    }
    for (int t = tid; t < LAT * STATE; t += 256) sM[t] = Wdec[t];   // M_0 = Wdec
    for (int t = tid; t < LAT * CTRL; t += 256) sNall[t] = g_Bm[b * LAT * CTRL + t];
#pragma unroll
    for (int p = 0; p < 4; p++) {
        int idx = tid + p * 256;
        *(float4*)&su[idx * 4] = *(const float4*)&u[((size_t)b * Tt + idx) * CTRL];
    }
    __syncthreads();

    // K_0 (sM == Wdec here)
    if (tid < STATE * CTRL) {
        int o = tid >> 2, c = tid & 3;
        float acc = 0.f;
        for (int i = 0; i < LAT; i++) acc += sM[i * STATE + o] * sNall[i * CTRL + c];
        g_K[(b * Dd) * STATE * CTRL + tid] = acc;
    }

    // N phase: N_k = N_{k-1} + E N_{k-1}; K_k via sM (still Wdec)
    for (int k = 1; k < Dd; k++) {
        float accN[4] = {0.f, 0.f, 0.f, 0.f};
        if (tid < 128) {
            const float* Np = &sNall[(k - 1) * 512];
#pragma unroll
            for (int c = 0; c < 4; c++) accN[c] = Np[tid * 4 + c];
            for (int l = 0; l < LAT; l++) {
                float e = sE[tid * PLD + l];
#pragma unroll
                for (int c = 0; c < 4; c++) accN[c] += e * Np[l * 4 + c];
            }
        }
        __syncthreads();
        if (tid < 128)
#pragma unroll
            for (int c = 0; c < 4; c++) sNall[k * 512 + tid * 4 + c] = accN[c];
        __syncthreads();
        if (tid < STATE * CTRL) {
            int o = tid >> 2, c = tid & 3;
            float acc = 0.f;
            for (int i = 0; i < LAT; i++)
                acc += sM[i * STATE + o] * sNall[k * 512 + i * CTRL + c];
            g_K[(b * Dd + k) * STATE * CTRL + tid] = acc;
        }
    }
    __syncthreads();

    // d_j = sum_r N_{7-r} u_{8j+r}
    {
        int i = tid & 127, jh = tid >> 7;
        for (int jj = 0; jj < 64; jj++) {
            int j = jj * 2 + jh;
            float acc = 0.f;
#pragma unroll
            for (int r = 0; r < Dd; r++) {
                float4 n = *(float4*)&sNall[(7 - r) * 512 + i * 4];
                float4 uu = *(float4*)&su[(8 * j + r) * 4];
                acc += dot4(n, uu);
            }
            g_d[((size_t)b * Jn + j) * LAT + i] = acc;
        }
    }

    // M phase: M_r = M_{r-1} + E^T M_{r-1}; write each to g_M
    for (int t = tid; t < LAT * STATE; t += 256)
        g_M[(size_t)(b * Dd) * LAT * STATE + t] = sM[t];
    {
        int i = tid & 127, oh = tid >> 7;
        int ob = oh ? 7 : 0, on = oh ? 6 : 7;
        for (int r = 1; r < Dd; r++) {
            float acc[7];
#pragma unroll
            for (int oo = 0; oo < 7; oo++)
                acc[oo] = (oo < on) ? sM[i * STATE + ob + oo] : 0.f;
            for (int l = 0; l < LAT; l++) {
                float e = sE[l * PLD + i];
#pragma unroll
                for (int oo = 0; oo < 7; oo++)
                    if (oo < on) acc[oo] += e * sM[l * STATE + ob + oo];
            }
            __syncthreads();
            for (int oo = 0; oo < on; oo++) sM[i * STATE + ob + oo] = acc[oo];
            __syncthreads();
            for (int t = tid; t < LAT * STATE; t += 256)
                g_M[(size_t)(b * Dd + r) * LAT * STATE + t] = sM[t];
        }
    }
}

// ---------------- decimated scan: 128 steps with A^8 ----------------
__global__ void __launch_bounds__(128, 3)
k_scan(const float* __restrict__ x_init, const float* __restrict__ Wenc,
       const float* __restrict__ benc) {
    int b = blockIdx.x;
    int i = threadIdx.x;

    __shared__ float zs[2][LAT];
    __shared__ float xi[16];

    ulonglong2 a[32];
    const ulonglong2* Ab = (const ulonglong2*)(g_A8 + (size_t)b * (LAT * LAT) + (size_t)i * LAT);
#pragma unroll
    for (int t = 0; t < 32; t++) a[t] = Ab[t];

    if (i < STATE) xi[i] = x_init[b * STATE + i];
    __syncthreads();

    float z0 = benc[i];
#pragma unroll
    for (int s = 0; s < STATE; s++) z0 += xi[s] * Wenc[s * LAT + i];
    zs[0][i] = z0;
    g_z8[(size_t)b * (Jn + 1) * LAT + i] = z0;
    __syncthreads();

    const float* db = g_d + (size_t)b * Jn * LAT;
    float ci = db[i];
    int cur = 0;

    for (int k = 0; k < Jn; k++) {
        float cnext = (k + 1 < Jn) ? db[(k + 1) * LAT + i] : 0.f;

        const ulonglong2* zv2 = (const ulonglong2*)zs[cur];
        unsigned long long acc0 = pack2(ci, 0.f);
        unsigned long long acc1 = 0ULL, acc2 = 0ULL, acc3 = 0ULL;
#pragma unroll
        for (int t = 0; t < 32; t += 2) {
            ulonglong2 zva = zv2[t];
            ulonglong2 zvb = zv2[t + 1];
            ffma2(acc0, a[t].x, zva.x);
            ffma2(acc1, a[t].y, zva.y);
            ffma2(acc2, a[t + 1].x, zvb.x);
            ffma2(acc3, a[t + 1].y, zvb.y);
        }
        float s0, s1, s2, s3, s4, s5, s6, s7;
        unpack2(acc0, s0, s1); unpack2(acc1, s2, s3);
        unpack2(acc2, s4, s5); unpack2(acc3, s6, s7);
        float zn = ((s0 + s2) + (s1 + s3)) + ((s4 + s6) + (s5 + s7));

        zs[cur ^ 1][i] = zn;
        g_z8[((size_t)b * (Jn + 1) + k + 1) * LAT + i] = zn;
        ci = cnext;
        __syncthreads();
        cur ^= 1;
    }
}

// ---------------- X GEMM: X[j][r*16+o] = z8[j] . M_r[:,o] ----------------
#define XP 132
__global__ void __launch_bounds__(256)
k_xg() {
    __align__(16) __shared__ float sZ[32 * XP];   // [kk][j], j=0..128
    __align__(16) __shared__ float sM2[32 * XP];  // [kk][r*16+o]
    int b = blockIdx.x, tid = threadIdx.x;
    int ry = tid >> 3;
    int cx = tid & 7;

    __align__(16) unsigned long long acc2[4][8];
#pragma unroll
    for (int q = 0; q < 4; q++)
#pragma unroll
        for (int p = 0; p < 8; p++) acc2[q][p] = 0ULL;
    float acc128 = 0.f;
    int r13 = 0, o13 = 0;
    if (tid < 104) { r13 = tid / 13; o13 = tid % 13; }

    for (int k0 = 0; k0 < 128; k0 += 32) {
        __syncthreads();
        for (int t = tid; t < 129 * 32; t += 256) {
            int j = t >> 5, kk = t & 31;
            sZ[kk * XP + j] = g_z8[((size_t)b * (Jn + 1) + j) * LAT + k0 + kk];
        }
        for (int t = tid; t < 32 * 128; t += 256) {
            int kk = t >> 7, col = t & 127;
            int r = col >> 4, o = col & 15;
            sM2[kk * XP + col] =
                (o < STATE) ? g_M[((size_t)(b * Dd + r) * LAT + k0 + kk) * STATE + o] : 0.f;
        }
        __syncthreads();
#pragma unroll
        for (int kk = 0; kk < 32; kk++) {
            float4 a4 = *(float4*)&sZ[kk * XP + ry * 4];
            ulonglong2 bb0 = *(ulonglong2*)&sM2[kk * XP + cx * 16];
            ulonglong2 bb1 = *(ulonglong2*)&sM2[kk * XP + cx * 16 + 4];
            ulonglong2 bb2 = *(ulonglong2*)&sM2[kk * XP + cx * 16 + 8];
            ulonglong2 bb3 = *(ulonglong2*)&sM2[kk * XP + cx * 16 + 12];
            unsigned long long bb[8] = {bb0.x, bb0.y, bb1.x, bb1.y, bb2.x, bb2.y, bb3.x, bb3.y};
            float av[4] = {a4.x, a4.y, a4.z, a4.w};
#pragma unroll
            for (int q = 0; q < 4; q++) {
                unsigned long long a2 = pack2(av[q], av[q]);
#pragma unroll
                for (int p = 0; p < 8; p++) ffma2(acc2[q][p], a2, bb[p]);
            }
        }
        if (tid < 104) {
            float accl = 0.f;
            for (int kk = 0; kk < 32; kk++)
                accl += sZ[kk * XP + 128] * sM2[kk * XP + r13 * 16 + o13];
            acc128 += accl;
        }
    }
    float* X = (float*)g_X4;
#pragma unroll
    for (int q = 0; q < 4; q++) {
        int j = ry * 4 + q;
        size_t base = ((size_t)b * (Jn + 1) + j) * 128 + cx * 16;
        *(float4*)&X[base]      = *(float4*)&acc2[q][0];
        *(float4*)&X[base + 4]  = *(float4*)&acc2[q][2];
        *(float4*)&X[base + 8]  = *(float4*)&acc2[q][4];
        *(float4*)&X[base + 12] = *(float4*)&acc2[q][6];
    }
    if (tid < 104)
        X[((size_t)b * (Jn + 1) + 128) * 128 + r13 * 16 + o13] = acc128;
}

// ---------------- final: u-corrections + bias + normalize + write out ----------------
__global__ void __launch_bounds__(256)
k_norm(const float* __restrict__ u, const float* __restrict__ bdec,
       float* __restrict__ outp) {
    int b = blockIdx.y, t0 = blockIdx.x * 256, tid = threadIdx.x;
    __shared__ float sK[Dd * STATE * CTRL];
    __shared__ float4 su[256];
    __shared__ float sb[STATE];
    __shared__ float sO[256 * STATE];

    for (int q = tid; q < Dd * STATE * CTRL; q += 256) sK[q] = g_K[b * Dd * STATE * CTRL + q];
    if (t0 + tid < Tt) su[tid] = *(const float4*)&u[((size_t)b * Tt + t0 + tid) * CTRL];
    if (tid < STATE) sb[tid] = bdec[tid];
    __syncthreads();

    int t = t0 + tid;
    if (t <= Tt) {
        int j = t >> 3, r = t & 7;
        const float* xr = (const float*)g_X4 + ((size_t)b * (Jn + 1) + j) * 128 + r * 16;
        float4 x0 = *(const float4*)&xr[0];
        float4 x1 = *(const float4*)&xr[4];
        float4 x2 = *(const float4*)&xr[8];
        float4 x3 = *(const float4*)&xr[12];
        float x[13] = {x0.x, x0.y, x0.z, x0.w, x1.x, x1.y, x1.z, x1.w,
                       x2.x, x2.y, x2.z, x2.w, x3.x};
#pragma unroll
        for (int o = 0; o < STATE; o++) x[o] += sb[o];
        for (int s = 0; s < r; s++) {
            float4 uu = su[tid - r + s];
            const float* Kp = &sK[(r - 1 - s) * STATE * CTRL];
#pragma unroll
            for (int o = 0; o < STATE; o++)
                x[o] += Kp[o * 4 + 0] * uu.x + Kp[o * 4 + 1] * uu.y +
                        Kp[o * 4 + 2] * uu.z + Kp[o * 4 + 3] * uu.w;
        }
        float nrm = sqrtf(x[3] * x[3] + x[4] * x[4] + x[5] * x[5] + x[6] * x[6]);
        float inv = 1.0f / fmaxf(nrm, 1e-12f);
        x[3] *= inv; x[4] *= inv; x[5] *= inv; x[6] *= inv;
#pragma unroll
        for (int o = 0; o < STATE; o++) sO[tid * STATE + o] = x[o];
    }
    __syncthreads();
    int nrow = Tt + 1 - t0;
    if (nrow > 256) nrow = 256;
    if (nrow < 0) nrow = 0;
    for (int q = tid; q < nrow * STATE; q += 256)
        outp[((size_t)b * (Tt + 1) + t0) * STATE + q] = sO[q];
}

// ---------------- launcher ----------------
extern "C" void kernel_launch(void* const* d_in, const int* in_sizes, int n_in,
                              void* d_out, int out_size) {
    const float* x_history = (const float*)d_in[0];
    const float* u_history = (const float*)d_in[1];
    const float* x_init    = (const float*)d_in[2];
    const float* u_future  = (const float*)d_in[4];
    const float* W_ctxt    = (const float*)d_in[6];
    const float* b_ctxt    = (const float*)d_in[7];
    const float* W_A       = (const float*)d_in[8];
    const float* b_A       = (const float*)d_in[9];
    const float* W_B       = (const float*)d_in[10];
    const float* b_B       = (const float*)d_in[11];
    const float* W_enc     = (const float*)d_in[12];
    const float* b_enc     = (const float*)d_in[13];
    const float* W_dec     = (const float*)d_in[14];
    const float* b_dec     = (const float*)d_in[15];
    float* out = (float*)d_out;

    const int POW_SMEM = 2 * 128 * PLD * 4;                       // 135168 B
    const int MND_SMEM = (128 * PLD + 128 * STATE + 8 * 128 * 4 + 1024 * 4) * 4;  // 107008 B
    cudaFuncSetAttribute(k_pow, cudaFuncAttributeMaxDynamicSharedMemorySize, POW_SMEM);
    cudaFuncSetAttribute(k_mnd, cudaFuncAttributeMaxDynamicSharedMemorySize, MND_SMEM);

    k_ctxt<<<Bn, 256>>>(x_history, u_history, W_ctxt, b_ctxt);
    k_gemmE_tc<<<dim3(128, 4), 256>>>(W_A);
    k_gemmB<<<Bn, 256>>>(W_B, b_B);

    k_pow<<<Bn, 256, POW_SMEM>>>(b_A);
    k_mnd<<<Bn, 256, MND_SMEM>>>(b_A, W_dec, u_future);

    k_scan<<<Bn, 128>>>(x_init, W_enc, b_enc);

    k_xg<<<Bn, 256>>>();
    k_norm<<<dim3(5, Bn), 256>>>(u_future, b_dec, out);
}

// round 9
// speedup vs baseline: 1.8587x; 1.0348x over previous
#include <cuda_runtime.h>
#include <mma.h>
#include <cstdint>

using namespace nvcuda;

// Problem constants
#define Bn    512
#define Hh    50
#define Tt    1024
#define STATE 13
#define CTRL  4
#define LAT   128
#define HID   256
#define Dd    8            // decimation factor
#define Jn    (Tt / Dd)    // 128 sequential steps

// ---------------- scratch (no allocations allowed) ----------------
__device__ float  g_h[Bn * HID];
__device__ float  g_E [(size_t)Bn * LAT * LAT];    // raw h@W_A product (bias NOT added)
__device__ float  g_A8[(size_t)Bn * LAT * LAT];    // A^8 (incl. identity)
__device__ float  g_Bm[Bn * LAT * CTRL];
__device__ float  g_M [(size_t)Bn * Dd * LAT * STATE]; // M_r = (A^T)^r Wdec
__device__ float  g_K [Bn * Dd * STATE * CTRL];    // K_k = Wdec^T A^k B
__device__ float  g_d [(size_t)Bn * Jn * LAT];     // d_j
__device__ float  g_z8[(size_t)Bn * (Jn + 1) * LAT];
__device__ float4 g_X4[(size_t)Bn * (Jn + 1) * 32];  // X rows 128-wide: [b][j][r*16+o]

// ---------------- f32x2 packed FMA helpers ----------------
__device__ __forceinline__ unsigned long long pack2(float x, float y) {
    unsigned long long r;
    asm("mov.b64 %0, {%1, %2};" : "=l"(r) : "f"(x), "f"(y));
    return r;
}
__device__ __forceinline__ void unpack2(unsigned long long v, float& x, float& y) {
    asm("mov.b64 {%0, %1}, %2;" : "=f"(x), "=f"(y) : "l"(v));
}
__device__ __forceinline__ void ffma2(unsigned long long& d, unsigned long long a,
                                      unsigned long long b) {
    asm("fma.rn.f32x2 %0, %1, %2, %3;" : "=l"(d) : "l"(a), "l"(b), "l"(d));
}
__device__ __forceinline__ float dot4(float4 a, float4 b) {
    return a.x * b.x + a.y * b.y + a.z * b.z + a.w * b.w;
}

// ---------------- wmma types ----------------
typedef wmma::fragment<wmma::matrix_a, 16, 16, 8, wmma::precision::tf32, wmma::row_major> FragA;
typedef wmma::fragment<wmma::matrix_b, 16, 16, 8, wmma::precision::tf32, wmma::row_major> FragBr;
typedef wmma::fragment<wmma::accumulator, 16, 16, 8, float> FragC;

__device__ __forceinline__ void cvt_tf32_a(FragA& f) {
#pragma unroll
    for (int e = 0; e < f.num_elements; e++) f.x[e] = wmma::__float_to_tf32(f.x[e]);
}
__device__ __forceinline__ void cvt_tf32_b(FragBr& f) {
#pragma unroll
    for (int e = 0; e < f.num_elements; e++) f.x[e] = wmma::__float_to_tf32(f.x[e]);
}

// ---------------- kernel 1: context mean + tanh MLP ----------------
__global__ void k_ctxt(const float* __restrict__ xh, const float* __restrict__ uh,
                       const float* __restrict__ Wc, const float* __restrict__ bc) {
    int b = blockIdx.x;
    int tid = threadIdx.x;
    __shared__ float m[STATE + CTRL];

    if (tid < STATE + CTRL) {
        float s = 0.f;
        if (tid < STATE) {
            const float* p = xh + (size_t)b * Hh * STATE + tid;
            for (int r = 0; r < Hh; r++) s += p[r * STATE];
        } else {
            const float* p = uh + (size_t)b * Hh * CTRL + (tid - STATE);
            for (int r = 0; r < Hh; r++) s += p[r * CTRL];
        }
        m[tid] = s * (1.0f / (float)Hh);
    }
    __syncthreads();

    float acc = bc[tid];
#pragma unroll
    for (int c = 0; c < STATE + CTRL; c++) acc += m[c] * Wc[c * HID + tid];
    g_h[b * HID + tid] = tanhf(acc);
}

// ---------------- kernel 2: E = h @ W_A (single-pass tf32) ----------------
// grid (128 n-tiles, 4 m-tiles). Stores fragments straight to g_E.
__global__ void __launch_bounds__(256)
k_gemmE_tc(const float* __restrict__ WA) {
    __shared__ float sA[128 * 36];
    __shared__ float sB[32 * 132];
    int tid = threadIdx.x, w = tid >> 5;
    int wm = w & 3, wn = w >> 2;
    int n0g = blockIdx.x * 128;
    int m0g = blockIdx.y * 128;

    FragC fc[2][4];
#pragma unroll
    for (int mt = 0; mt < 2; mt++)
#pragma unroll
        for (int nt = 0; nt < 4; nt++) wmma::fill_fragment(fc[mt][nt], 0.f);

    for (int k0 = 0; k0 < HID; k0 += 32) {
        __syncthreads();
#pragma unroll
        for (int p = 0; p < 4; p++) {
            int idx = tid + p * 256;
            int row = idx >> 3, kq = (idx & 7) * 4;
            *(float4*)&sA[row * 36 + kq] =
                *(const float4*)&g_h[(m0g + row) * HID + k0 + kq];
        }
#pragma unroll
        for (int p = 0; p < 4; p++) {
            int idx = tid + p * 256;
            int kkb = idx >> 5, c4 = (idx & 31) * 4;
            *(float4*)&sB[kkb * 132 + c4] =
                *(const float4*)&WA[(size_t)(k0 + kkb) * (LAT * LAT) + n0g + c4];
        }
        __syncthreads();
#pragma unroll
        for (int kk8 = 0; kk8 < 4; kk8++) {
            FragA fa[2];
#pragma unroll
            for (int mt = 0; mt < 2; mt++) {
                wmma::load_matrix_sync(fa[mt], &sA[(wm * 32 + mt * 16) * 36 + kk8 * 8], 36);
                cvt_tf32_a(fa[mt]);
            }
#pragma unroll
            for (int nt = 0; nt < 4; nt++) {
                FragBr fb;
                wmma::load_matrix_sync(fb, &sB[(kk8 * 8) * 132 + wn * 64 + nt * 16], 132);
                cvt_tf32_b(fb);
                wmma::mma_sync(fc[0][nt], fa[0], fb, fc[0][nt]);
                wmma::mma_sync(fc[1][nt], fa[1], fb, fc[1][nt]);
            }
        }
    }
#pragma unroll
    for (int mt = 0; mt < 2; mt++)
#pragma unroll
        for (int nt = 0; nt < 4; nt++)
            wmma::store_matrix_sync(
                &g_E[(size_t)(m0g + wm * 32 + mt * 16) * (LAT * LAT) +
                     n0g + wn * 64 + nt * 16],
                fc[mt][nt], LAT * LAT, wmma::mem_row_major);
}

// ---------------- kernel 3: B_mat = h @ W_B + b_B ----------------
__global__ void k_gemmB(const float* __restrict__ WB, const float* __restrict__ bB) {
    int b = blockIdx.x;
    int tid = threadIdx.x;
    __shared__ float hs[HID];
    hs[tid] = g_h[b * HID + tid];
    __syncthreads();
    for (int c = tid; c < LAT * CTRL; c += 256) {
        float acc = bB[c];
#pragma unroll 8
        for (int k = 0; k < HID; k++) acc += hs[k] * WB[k * (LAT * CTRL) + c];
        g_Bm[b * (LAT * CTRL) + c] = acc;
    }
}

// ---------------- fused 3 squarings in smem (tf32): A^8 ----------------
// One CTA (512 thr, 16 warps) per batch. X = E (+bias). 3 rounds Y = X@X + 2X (+I last).
#define PLD 132
__global__ void __launch_bounds__(512)
k_pow(const float* __restrict__ bA) {
    extern __shared__ float dsm[];
    float* sX = dsm;
    float* sY = dsm + 128 * PLD;
    int b = blockIdx.x, tid = threadIdx.x, w = tid >> 5;
    int wm = w & 3, wn = w >> 2;        // 4x4 warp grid, each 32x32
    const float* Eb = g_E + (size_t)b * (LAT * LAT);

    // load E + bias
#pragma unroll
    for (int p = 0; p < 8; p++) {
        int idx = tid + p * 512;
        int row = idx >> 5, c4 = (idx & 31) * 4;
        float4 e = *(const float4*)&Eb[row * 128 + c4];
        float4 bb = *(const float4*)&bA[row * 128 + c4];
        e.x += bb.x; e.y += bb.y; e.z += bb.z; e.w += bb.w;
        *(float4*)&sX[row * PLD + c4] = e;
    }
    __syncthreads();

    float* pX = sX;
    float* pY = sY;
    for (int rnd = 0; rnd < 3; rnd++) {
        FragC fc[2][2];
#pragma unroll
        for (int mt = 0; mt < 2; mt++)
#pragma unroll
            for (int nt = 0; nt < 2; nt++) wmma::fill_fragment(fc[mt][nt], 0.f);

#pragma unroll 4
        for (int kk = 0; kk < 16; kk++) {
            FragA fa[2];
#pragma unroll
            for (int mt = 0; mt < 2; mt++) {
                wmma::load_matrix_sync(fa[mt], &pX[(wm * 32 + mt * 16) * PLD + kk * 8], PLD);
                cvt_tf32_a(fa[mt]);
            }
#pragma unroll
            for (int nt = 0; nt < 2; nt++) {
                FragBr fb;
                wmma::load_matrix_sync(fb, &pX[(kk * 8) * PLD + wn * 32 + nt * 16], PLD);
                cvt_tf32_b(fb);
                wmma::mma_sync(fc[0][nt], fa[0], fb, fc[0][nt]);
                wmma::mma_sync(fc[1][nt], fa[1], fb, fc[1][nt]);
            }
        }
#pragma unroll
        for (int mt = 0; mt < 2; mt++)
#pragma unroll
            for (int nt = 0; nt < 2; nt++)
                wmma::store_matrix_sync(&pY[(wm * 32 + mt * 16) * PLD + wn * 32 + nt * 16],
                                        fc[mt][nt], PLD, wmma::mem_row_major);
        __syncthreads();
        // elementwise: Y += 2X (+I on last round)
#pragma unroll
        for (int p = 0; p < 8; p++) {
            int idx = tid + p * 512;
            int row = idx >> 5, c4 = (idx & 31) * 4;
            float4 y = *(float4*)&pY[row * PLD + c4];
            float4 x = *(float4*)&pX[row * PLD + c4];
            y.x += 2.f * x.x; y.y += 2.f * x.y; y.z += 2.f * x.z; y.w += 2.f * x.w;
            if (rnd == 2) {
                int dq = row - c4;
                if (dq >= 0 && dq < 4) ((float*)&y)[dq] += 1.f;
            }
            *(float4*)&pY[row * PLD + c4] = y;
        }
        __syncthreads();
        float* t = pX; pX = pY; pY = t;
    }

    float* A8b = g_A8 + (size_t)b * (LAT * LAT);
#pragma unroll
    for (int p = 0; p < 8; p++) {
        int idx = tid + p * 512;
        int row = idx >> 5, c4 = (idx & 31) * 4;
        *(float4*)&A8b[row * 128 + c4] = *(float4*)&pX[row * PLD + c4];
    }
}

// ---------------- fused M/N/K/d with E smem-resident ----------------
__global__ void __launch_bounds__(256)
k_mnd(const float* __restrict__ bA, const float* __restrict__ Wdec,
      const float* __restrict__ u) {
    extern __shared__ float dsm[];
    float* sE    = dsm;                    // 128*132
    float* sM    = sE + 128 * PLD;         // 128*13
    float* sNall = sM + 128 * STATE;       // 8*128*4
    float* su    = sNall + 8 * 128 * 4;    // 1024*4
    int b = blockIdx.x, tid = threadIdx.x;
    const float* Eb = g_E + (size_t)b * (LAT * LAT);

    // load E + bias
#pragma unroll
    for (int p = 0; p < 16; p++) {
        int idx = tid + p * 256;
        int row = idx >> 5, c4 = (idx & 31) * 4;
        float4 e = *(const float4*)&Eb[row * 128 + c4];
        float4 bb = *(const float4*)&bA[row * 128 + c4];
        e.x += bb.x; e.y += bb.y; e.z += bb.z; e.w += bb.w;
        *(float4*)&sE[row * PLD + c4] = e;
    }
    for (int t = tid; t < LAT * STATE; t += 256) sM[t] = Wdec[t];   // M_0 = Wdec
    for (int t = tid; t < LAT * CTRL; t += 256) sNall[t] = g_Bm[b * LAT * CTRL + t];
#pragma unroll
    for (int p = 0; p < 4; p++) {
        int idx = tid + p * 256;
        *(float4*)&su[idx * 4] = *(const float4*)&u[((size_t)b * Tt + idx) * CTRL];
    }
    __syncthreads();

    // K_0 (sM == Wdec here)
    if (tid < STATE * CTRL) {
        int o = tid >> 2, c = tid & 3;
        float acc = 0.f;
        for (int i = 0; i < LAT; i++) acc += sM[i * STATE + o] * sNall[i * CTRL + c];
        g_K[(b * Dd) * STATE * CTRL + tid] = acc;
    }

    // N phase: N_k = N_{k-1} + E N_{k-1}; K_k via sM (still Wdec)
    for (int k = 1; k < Dd; k++) {
        float accN[4] = {0.f, 0.f, 0.f, 0.f};
        if (tid < 128) {
            const float* Np = &sNall[(k - 1) * 512];
#pragma unroll
            for (int c = 0; c < 4; c++) accN[c] = Np[tid * 4 + c];
            for (int l = 0; l < LAT; l++) {
                float e = sE[tid * PLD + l];
#pragma unroll
                for (int c = 0; c < 4; c++) accN[c] += e * Np[l * 4 + c];
            }
        }
        __syncthreads();
        if (tid < 128)
#pragma unroll
            for (int c = 0; c < 4; c++) sNall[k * 512 + tid * 4 + c] = accN[c];
        __syncthreads();
        if (tid < STATE * CTRL) {
            int o = tid >> 2, c = tid & 3;
            float acc = 0.f;
            for (int i = 0; i < LAT; i++)
                acc += sM[i * STATE + o] * sNall[k * 512 + i * CTRL + c];
            g_K[(b * Dd + k) * STATE * CTRL + tid] = acc;
        }
    }
    __syncthreads();

    // d_j = sum_r N_{7-r} u_{8j+r}
    {
        int i = tid & 127, jh = tid >> 7;
        for (int jj = 0; jj < 64; jj++) {
            int j = jj * 2 + jh;
            float acc = 0.f;
#pragma unroll
            for (int r = 0; r < Dd; r++) {
                float4 n = *(float4*)&sNall[(7 - r) * 512 + i * 4];
                float4 uu = *(float4*)&su[(8 * j + r) * 4];
                acc += dot4(n, uu);
            }
            g_d[((size_t)b * Jn + j) * LAT + i] = acc;
        }
    }

    // M phase: M_r = M_{r-1} + E^T M_{r-1}; write each to g_M
    for (int t = tid; t < LAT * STATE; t += 256)
        g_M[(size_t)(b * Dd) * LAT * STATE + t] = sM[t];
    {
        int i = tid & 127, oh = tid >> 7;
        int ob = oh ? 7 : 0, on = oh ? 6 : 7;
        for (int r = 1; r < Dd; r++) {
            float acc[7];
#pragma unroll
            for (int oo = 0; oo < 7; oo++)
                acc[oo] = (oo < on) ? sM[i * STATE + ob + oo] : 0.f;
            for (int l = 0; l < LAT; l++) {
                float e = sE[l * PLD + i];
#pragma unroll
                for (int oo = 0; oo < 7; oo++)
                    if (oo < on) acc[oo] += e * sM[l * STATE + ob + oo];
            }
            __syncthreads();
            for (int oo = 0; oo < on; oo++) sM[i * STATE + ob + oo] = acc[oo];
            __syncthreads();
            for (int t = tid; t < LAT * STATE; t += 256)
                g_M[(size_t)(b * Dd + r) * LAT * STATE + t] = sM[t];
        }
    }
}

// ---------------- decimated scan: 128 steps with A^8 (1 wave @ occ 4) ----------------
__global__ void __launch_bounds__(128, 4)
k_scan(const float* __restrict__ x_init, const float* __restrict__ Wenc,
       const float* __restrict__ benc) {
    int b = blockIdx.x;
    int i = threadIdx.x;

    __shared__ float zs[2][LAT];
    __shared__ float xi[16];

    ulonglong2 a[32];
    const ulonglong2* Ab = (const ulonglong2*)(g_A8 + (size_t)b * (LAT * LAT) + (size_t)i * LAT);
#pragma unroll
    for (int t = 0; t < 32; t++) a[t] = Ab[t];

    if (i < STATE) xi[i] = x_init[b * STATE + i];
    __syncthreads();

    float z0 = benc[i];
#pragma unroll
    for (int s = 0; s < STATE; s++) z0 += xi[s] * Wenc[s * LAT + i];
    zs[0][i] = z0;
    g_z8[(size_t)b * (Jn + 1) * LAT + i] = z0;
    __syncthreads();

    const float* db = g_d + (size_t)b * Jn * LAT;
    float ci = db[i];
    int cur = 0;

    for (int k = 0; k < Jn; k++) {
        float cnext = (k + 1 < Jn) ? db[(k + 1) * LAT + i] : 0.f;

        const ulonglong2* zv2 = (const ulonglong2*)zs[cur];
        unsigned long long acc0 = pack2(ci, 0.f);
        unsigned long long acc1 = 0ULL, acc2 = 0ULL, acc3 = 0ULL;
#pragma unroll
        for (int t = 0; t < 32; t += 2) {
            ulonglong2 zva = zv2[t];
            ulonglong2 zvb = zv2[t + 1];
            ffma2(acc0, a[t].x, zva.x);
            ffma2(acc1, a[t].y, zva.y);
            ffma2(acc2, a[t + 1].x, zvb.x);
            ffma2(acc3, a[t + 1].y, zvb.y);
        }
        float s0, s1, s2, s3, s4, s5, s6, s7;
        unpack2(acc0, s0, s1); unpack2(acc1, s2, s3);
        unpack2(acc2, s4, s5); unpack2(acc3, s6, s7);
        float zn = ((s0 + s2) + (s1 + s3)) + ((s4 + s6) + (s5 + s7));

        zs[cur ^ 1][i] = zn;
        g_z8[((size_t)b * (Jn + 1) + k + 1) * LAT + i] = zn;
        ci = cnext;
        __syncthreads();
        cur ^= 1;
    }
}

// ---------------- X GEMM: X[j][r*16+o] = z8[j] . M_r[:,o] ----------------
#define XP 132
__global__ void __launch_bounds__(256)
k_xg() {
    __align__(16) __shared__ float sZ[32 * XP];   // [kk][j], j=0..128
    __align__(16) __shared__ float sM2[32 * XP];  // [kk][r*16+o]
    int b = blockIdx.x, tid = threadIdx.x;
    int ry = tid >> 3;
    int cx = tid & 7;

    __align__(16) unsigned long long acc2[4][8];
#pragma unroll
    for (int q = 0; q < 4; q++)
#pragma unroll
        for (int p = 0; p < 8; p++) acc2[q][p] = 0ULL;
    float acc128 = 0.f;
    int r13 = 0, o13 = 0;
    if (tid < 104) { r13 = tid / 13; o13 = tid % 13; }

    for (int k0 = 0; k0 < 128; k0 += 32) {
        __syncthreads();
        for (int t = tid; t < 129 * 32; t += 256) {
            int j = t >> 5, kk = t & 31;
            sZ[kk * XP + j] = g_z8[((size_t)b * (Jn + 1) + j) * LAT + k0 + kk];
        }
        for (int t = tid; t < 32 * 128; t += 256) {
            int kk = t >> 7, col = t & 127;
            int r = col >> 4, o = col & 15;
            sM2[kk * XP + col] =
                (o < STATE) ? g_M[((size_t)(b * Dd + r) * LAT + k0 + kk) * STATE + o] : 0.f;
        }
        __syncthreads();
#pragma unroll
        for (int kk = 0; kk < 32; kk++) {
            float4 a4 = *(float4*)&sZ[kk * XP + ry * 4];
            ulonglong2 bb0 = *(ulonglong2*)&sM2[kk * XP + cx * 16];
            ulonglong2 bb1 = *(ulonglong2*)&sM2[kk * XP + cx * 16 + 4];
            ulonglong2 bb2 = *(ulonglong2*)&sM2[kk * XP + cx * 16 + 8];
            ulonglong2 bb3 = *(ulonglong2*)&sM2[kk * XP + cx * 16 + 12];
            unsigned long long bb[8] = {bb0.x, bb0.y, bb1.x, bb1.y, bb2.x, bb2.y, bb3.x, bb3.y};
            float av[4] = {a4.x, a4.y, a4.z, a4.w};
#pragma unroll
            for (int q = 0; q < 4; q++) {
                unsigned long long a2 = pack2(av[q], av[q]);
#pragma unroll
                for (int p = 0; p < 8; p++) ffma2(acc2[q][p], a2, bb[p]);
            }
        }
        if (tid < 104) {
            float accl = 0.f;
            for (int kk = 0; kk < 32; kk++)
                accl += sZ[kk * XP + 128] * sM2[kk * XP + r13 * 16 + o13];
            acc128 += accl;
        }
    }
    float* X = (float*)g_X4;
#pragma unroll
    for (int q = 0; q < 4; q++) {
        int j = ry * 4 + q;
        size_t base = ((size_t)b * (Jn + 1) + j) * 128 + cx * 16;
        *(float4*)&X[base]      = *(float4*)&acc2[q][0];
        *(float4*)&X[base + 4]  = *(float4*)&acc2[q][2];
        *(float4*)&X[base + 8]  = *(float4*)&acc2[q][4];
        *(float4*)&X[base + 12] = *(float4*)&acc2[q][6];
    }
    if (tid < 104)
        X[((size_t)b * (Jn + 1) + 128) * 128 + r13 * 16 + o13] = acc128;
}

// ---------------- final: u-corrections + bias + normalize + write out ----------------
__global__ void __launch_bounds__(256)
k_norm(const float* __restrict__ u, const float* __restrict__ bdec,
       float* __restrict__ outp) {
    int b = blockIdx.y, t0 = blockIdx.x * 256, tid = threadIdx.x;
    __shared__ float sK[Dd * STATE * CTRL];
    __shared__ float4 su[256];
    __shared__ float sb[STATE];
    __shared__ float sO[256 * STATE];

    for (int q = tid; q < Dd * STATE * CTRL; q += 256) sK[q] = g_K[b * Dd * STATE * CTRL + q];
    if (t0 + tid < Tt) su[tid] = *(const float4*)&u[((size_t)b * Tt + t0 + tid) * CTRL];
    if (tid < STATE) sb[tid] = bdec[tid];
    __syncthreads();

    int t = t0 + tid;
    if (t <= Tt) {
        int j = t >> 3, r = t & 7;
        const float* xr = (const float*)g_X4 + ((size_t)b * (Jn + 1) + j) * 128 + r * 16;
        float4 x0 = *(const float4*)&xr[0];
        float4 x1 = *(const float4*)&xr[4];
        float4 x2 = *(const float4*)&xr[8];
        float4 x3 = *(const float4*)&xr[12];
        float x[13] = {x0.x, x0.y, x0.z, x0.w, x1.x, x1.y, x1.z, x1.w,
                       x2.x, x2.y, x2.z, x2.w, x3.x};
#pragma unroll
        for (int o = 0; o < STATE; o++) x[o] += sb[o];
        for (int s = 0; s < r; s++) {
            float4 uu = su[tid - r + s];
            const float* Kp = &sK[(r - 1 - s) * STATE * CTRL];
#pragma unroll
            for (int o = 0; o < STATE; o++)
                x[o] += Kp[o * 4 + 0] * uu.x + Kp[o * 4 + 1] * uu.y +
                        Kp[o * 4 + 2] * uu.z + Kp[o * 4 + 3] * uu.w;
        }
        float nrm = sqrtf(x[3] * x[3] + x[4] * x[4] + x[5] * x[5] + x[6] * x[6]);
        float inv = 1.0f / fmaxf(nrm, 1e-12f);
        x[3] *= inv; x[4] *= inv; x[5] *= inv; x[6] *= inv;
#pragma unroll
        for (int o = 0; o < STATE; o++) sO[tid * STATE + o] = x[o];
    }
    __syncthreads();
    int nrow = Tt + 1 - t0;
    if (nrow > 256) nrow = 256;
    if (nrow < 0) nrow = 0;
    for (int q = tid; q < nrow * STATE; q += 256)
        outp[((size_t)b * (Tt + 1) + t0) * STATE + q] = sO[q];
}

// ---------------- launcher ----------------
extern "C" void kernel_launch(void* const* d_in, const int* in_sizes, int n_in,
                              void* d_out, int out_size) {
    const float* x_history = (const float*)d_in[0];
    const float* u_history = (const float*)d_in[1];
    const float* x_init    = (const float*)d_in[2];
    const float* u_future  = (const float*)d_in[4];
    const float* W_ctxt    = (const float*)d_in[6];
    const float* b_ctxt    = (const float*)d_in[7];
    const float* W_A       = (const float*)d_in[8];
    const float* b_A       = (const float*)d_in[9];
    const float* W_B       = (const float*)d_in[10];
    const float* b_B       = (const float*)d_in[11];
    const float* W_enc     = (const float*)d_in[12];
    const float* b_enc     = (const float*)d_in[13];
    const float* W_dec     = (const float*)d_in[14];
    const float* b_dec     = (const float*)d_in[15];
    float* out = (float*)d_out;

    const int POW_SMEM = 2 * 128 * PLD * 4;                       // 135168 B
    const int MND_SMEM = (128 * PLD + 128 * STATE + 8 * 128 * 4 + 1024 * 4) * 4;  // 107008 B
    cudaFuncSetAttribute(k_pow, cudaFuncAttributeMaxDynamicSharedMemorySize, POW_SMEM);
    cudaFuncSetAttribute(k_mnd, cudaFuncAttributeMaxDynamicSharedMemorySize, MND_SMEM);

    k_ctxt<<<Bn, 256>>>(x_history, u_history, W_ctxt, b_ctxt);
    k_gemmE_tc<<<dim3(128, 4), 256>>>(W_A);
    k_gemmB<<<Bn, 256>>>(W_B, b_B);

    k_pow<<<Bn, 512, POW_SMEM>>>(b_A);
    k_mnd<<<Bn, 256, MND_SMEM>>>(b_A, W_dec, u_future);

    k_scan<<<Bn, 128>>>(x_init, W_enc, b_enc);

    k_xg<<<Bn, 256>>>();
    k_norm<<<dim3(5, Bn), 256>>>(u_future, b_dec, out);
}